// round 2
// baseline (speedup 1.0000x reference)
#include <cuda_runtime.h>

// Problem constants
#define BB 8
#define NN 2048
#define DD 512
#define CC 4096
#define MM (BB*NN)   // 16384 rows of x

// ---------------- scratch (device globals; fully rewritten each launch) ----
__device__ float g_implicit[CC * DD];   // codebook @ W^T   [4096,512]  (8 MB)
__device__ float g_halfnorm[CC];        // 0.5*||implicit_c||^2
__device__ int   g_idx[MM];             // argmin indices
__device__ float g_commit[MM];          // per-row commit sums

// ===========================================================================
// Kernel 1: implicit = codebook @ W^T     (NT GEMM, fp32 SIMT)
// C[c,j] = sum_k A[c,k] * W[j,k];  tiles 128x128x8, 256 threads, 8x8/thread
// ===========================================================================
__global__ __launch_bounds__(256) void k_implicit(const float* __restrict__ A,
                                                  const float* __restrict__ Wm) {
    __shared__ float As[8][128];
    __shared__ float Bs[8][128];
    const int tid = threadIdx.x;
    const int tx = tid & 15, ty = tid >> 4;
    const int m0 = blockIdx.x * 128;      // codebook rows
    const int n0 = blockIdx.y * 128;      // output cols (rows of W)
    const int lr = tid >> 1;              // 0..127
    const int lk = (tid & 1) * 4;         // 0 or 4

    float acc[2][2][4][4];
#pragma unroll
    for (int a = 0; a < 2; a++)
#pragma unroll
        for (int b = 0; b < 2; b++)
#pragma unroll
            for (int i = 0; i < 4; i++)
#pragma unroll
                for (int j = 0; j < 4; j++) acc[a][b][i][j] = 0.f;

    for (int k0 = 0; k0 < DD; k0 += 8) {
        float4 av = *(const float4*)&A[(size_t)(m0 + lr) * DD + k0 + lk];
        float4 bv = *(const float4*)&Wm[(size_t)(n0 + lr) * DD + k0 + lk];
        __syncthreads();
        As[lk + 0][lr] = av.x; As[lk + 1][lr] = av.y; As[lk + 2][lr] = av.z; As[lk + 3][lr] = av.w;
        Bs[lk + 0][lr] = bv.x; Bs[lk + 1][lr] = bv.y; Bs[lk + 2][lr] = bv.z; Bs[lk + 3][lr] = bv.w;
        __syncthreads();
#pragma unroll
        for (int kk = 0; kk < 8; kk++) {
            float4 a0 = *(const float4*)&As[kk][ty * 4];
            float4 a1 = *(const float4*)&As[kk][64 + ty * 4];
            float4 b0 = *(const float4*)&Bs[kk][tx * 4];
            float4 b1 = *(const float4*)&Bs[kk][64 + tx * 4];
            float ar[8] = {a0.x, a0.y, a0.z, a0.w, a1.x, a1.y, a1.z, a1.w};
            float br[8] = {b0.x, b0.y, b0.z, b0.w, b1.x, b1.y, b1.z, b1.w};
#pragma unroll
            for (int ih = 0; ih < 2; ih++)
#pragma unroll
                for (int i = 0; i < 4; i++)
#pragma unroll
                    for (int jh = 0; jh < 2; jh++)
#pragma unroll
                        for (int j = 0; j < 4; j++)
                            acc[ih][jh][i][j] += ar[ih * 4 + i] * br[jh * 4 + j];
        }
    }
#pragma unroll
    for (int ih = 0; ih < 2; ih++)
#pragma unroll
        for (int i = 0; i < 4; i++) {
            int rm = m0 + ih * 64 + ty * 4 + i;
#pragma unroll
            for (int jh = 0; jh < 2; jh++) {
                int cn = n0 + jh * 64 + tx * 4;
                float4 v = make_float4(acc[ih][jh][i][0], acc[ih][jh][i][1],
                                       acc[ih][jh][i][2], acc[ih][jh][i][3]);
                *(float4*)&g_implicit[(size_t)rm * DD + cn] = v;
            }
        }
}

// ===========================================================================
// Kernel 2: halfnorm[c] = 0.5 * ||implicit[c]||^2   (one warp per row)
// ===========================================================================
__global__ __launch_bounds__(256) void k_halfnorm() {
    int warp = threadIdx.x >> 5, lane = threadIdx.x & 31;
    int row = blockIdx.x * 8 + warp;
    const float* p = g_implicit + (size_t)row * DD;
    float s = 0.f;
#pragma unroll
    for (int k = 0; k < DD / 32; k++) {
        float v = p[lane + 32 * k];
        s += v * v;
    }
#pragma unroll
    for (int o = 16; o > 0; o >>= 1) s += __shfl_xor_sync(0xffffffff, s, o);
    if (lane == 0) g_halfnorm[row] = 0.5f * s;
}

// ===========================================================================
// Kernel 3: fused score-GEMM + argmin.
// score(m,c) = 0.5||imp_c||^2 - dot(x_m, imp_c)   (same argmin as full d2)
// Block handles 128 x-rows, loops over all 32 c-tiles of 128.
// ===========================================================================
__global__ __launch_bounds__(256) void k_argmin(const float* __restrict__ X,
                                                float* __restrict__ out_idx_f) {
    __shared__ float As[8][128];
    __shared__ float Bs[8][128];
    __shared__ float redv[128][17];
    __shared__ int   redi[128][17];
    __shared__ float bestv[128];
    __shared__ int   besti[128];

    const int tid = threadIdx.x;
    const int tx = tid & 15, ty = tid >> 4;
    const int m0 = blockIdx.x * 128;
    const int lr = tid >> 1;
    const int lk = (tid & 1) * 4;

    if (tid < 128) { bestv[tid] = 3.4e38f; besti[tid] = 0; }
    __syncthreads();

    for (int nt = 0; nt < CC / 128; nt++) {
        const int c0 = nt * 128;
        float acc[2][2][4][4];
#pragma unroll
        for (int a = 0; a < 2; a++)
#pragma unroll
            for (int b = 0; b < 2; b++)
#pragma unroll
                for (int i = 0; i < 4; i++)
#pragma unroll
                    for (int j = 0; j < 4; j++) acc[a][b][i][j] = 0.f;

        for (int k0 = 0; k0 < DD; k0 += 8) {
            float4 av = *(const float4*)&X[(size_t)(m0 + lr) * DD + k0 + lk];
            float4 bv = *(const float4*)&g_implicit[(size_t)(c0 + lr) * DD + k0 + lk];
            __syncthreads();
            As[lk + 0][lr] = av.x; As[lk + 1][lr] = av.y; As[lk + 2][lr] = av.z; As[lk + 3][lr] = av.w;
            Bs[lk + 0][lr] = bv.x; Bs[lk + 1][lr] = bv.y; Bs[lk + 2][lr] = bv.z; Bs[lk + 3][lr] = bv.w;
            __syncthreads();
#pragma unroll
            for (int kk = 0; kk < 8; kk++) {
                float4 a0 = *(const float4*)&As[kk][ty * 4];
                float4 a1 = *(const float4*)&As[kk][64 + ty * 4];
                float4 b0 = *(const float4*)&Bs[kk][tx * 4];
                float4 b1 = *(const float4*)&Bs[kk][64 + tx * 4];
                float ar[8] = {a0.x, a0.y, a0.z, a0.w, a1.x, a1.y, a1.z, a1.w};
                float br[8] = {b0.x, b0.y, b0.z, b0.w, b1.x, b1.y, b1.z, b1.w};
#pragma unroll
                for (int ih = 0; ih < 2; ih++)
#pragma unroll
                    for (int i = 0; i < 4; i++)
#pragma unroll
                        for (int jh = 0; jh < 2; jh++)
#pragma unroll
                            for (int j = 0; j < 4; j++)
                                acc[ih][jh][i][j] += ar[ih * 4 + i] * br[jh * 4 + j];
            }
        }

        // per-thread argmin across its 8 cols, for each of its 8 rows
        float4 hn0 = *(const float4*)&g_halfnorm[c0 + tx * 4];
        float4 hn1 = *(const float4*)&g_halfnorm[c0 + 64 + tx * 4];
        float hn[2][4] = {{hn0.x, hn0.y, hn0.z, hn0.w}, {hn1.x, hn1.y, hn1.z, hn1.w}};
#pragma unroll
        for (int ih = 0; ih < 2; ih++)
#pragma unroll
            for (int i = 0; i < 4; i++) {
                int r = ih * 64 + ty * 4 + i;
                float mv = 3.4e38f; int mc = 0;
#pragma unroll
                for (int jh = 0; jh < 2; jh++)
#pragma unroll
                    for (int j = 0; j < 4; j++) {
                        float s = hn[jh][j] - acc[ih][jh][i][j];
                        int col = jh * 64 + tx * 4 + j;
                        if (s < mv) { mv = s; mc = col; }
                    }
                redv[r][tx] = mv;
                redi[r][tx] = c0 + mc;
            }
        __syncthreads();
        if (tid < 128) {
            float mv = bestv[tid]; int mi = besti[tid];
#pragma unroll
            for (int t = 0; t < 16; t++) {
                float v = redv[tid][t];
                if (v < mv) { mv = v; mi = redi[tid][t]; }
            }
            bestv[tid] = mv; besti[tid] = mi;
        }
        // next iteration's first __syncthreads() protects redv reuse
    }
    __syncthreads();
    if (tid < 128) {
        int gm = m0 + tid;
        g_idx[gm] = besti[tid];
        out_idx_f[gm] = (float)besti[tid];
    }
}

// ===========================================================================
// Kernel 4: rotation trick + per-row commit sum. One block per x-row.
// ===========================================================================
__global__ __launch_bounds__(128) void k_rot(const float* __restrict__ X,
                                             float* __restrict__ outq) {
    __shared__ float red[4][4];   // [warp][stat]
    const int m = blockIdx.x;
    const int t = threadIdx.x;
    const float* xr = X + (size_t)m * DD;
    const float* qr = g_implicit + (size_t)g_idx[m] * DD;

    float4 xv = ((const float4*)xr)[t];
    float4 qv = ((const float4*)qr)[t];

    float sx  = xv.x * xv.x + xv.y * xv.y + xv.z * xv.z + xv.w * xv.w;
    float sq  = qv.x * qv.x + qv.y * qv.y + qv.z * qv.z + qv.w * qv.w;
    float sxq = xv.x * qv.x + xv.y * qv.y + xv.z * qv.z + xv.w * qv.w;
    float d0 = xv.x - qv.x + 1e-6f, d1 = xv.y - qv.y + 1e-6f;
    float d2 = xv.z - qv.z + 1e-6f, d3 = xv.w - qv.w + 1e-6f;
    float sc = d0 * d0 + d1 * d1 + d2 * d2 + d3 * d3;

#pragma unroll
    for (int o = 16; o > 0; o >>= 1) {
        sx  += __shfl_xor_sync(0xffffffff, sx, o);
        sq  += __shfl_xor_sync(0xffffffff, sq, o);
        sxq += __shfl_xor_sync(0xffffffff, sxq, o);
        sc  += __shfl_xor_sync(0xffffffff, sc, o);
    }
    int warp = t >> 5, lane = t & 31;
    if (lane == 0) { red[warp][0] = sx; red[warp][1] = sq; red[warp][2] = sxq; red[warp][3] = sc; }
    __syncthreads();
    // fixed-order cross-warp combine (deterministic, identical on all threads)
    sx  = red[0][0] + red[1][0] + red[2][0] + red[3][0];
    sq  = red[0][1] + red[1][1] + red[2][1] + red[3][1];
    sxq = red[0][2] + red[1][2] + red[2][2] + red[3][2];
    sc  = red[0][3] + red[1][3] + red[2][3] + red[3][3];

    if (t == 0) g_commit[m] = sc;

    float norm_x = sqrtf(sx), norm_q = sqrtf(sq);
    float nx = fmaxf(norm_x, 1e-6f);
    float nq = fmaxf(norm_q, 1e-6f);
    float uq2 = sx / (nx * nx) + sq / (nq * nq) + 2.f * sxq / (nx * nq);
    float nuq = sqrtf(fmaxf(uq2, 0.f));
    float wden = fmaxf(nuq, 1e-12f);
    float e_w = (sx / nx + sxq / nq) / wden;   // dot(x, uq)/||uq||
    float e_u = sx / nx;                        // dot(x, u)
    float c1 = 2.f * e_w / wden;
    float c2 = 2.f * e_u;
    float scale = norm_q / nx;
    float coef_x = (1.f - c1 / nx) * scale;
    float coef_q = ((c2 - c1) / nq) * scale;

    float4 ov;
    ov.x = coef_x * xv.x + coef_q * qv.x;
    ov.y = coef_x * xv.y + coef_q * qv.y;
    ov.z = coef_x * xv.z + coef_q * qv.z;
    ov.w = coef_x * xv.w + coef_q * qv.w;
    ((float4*)(outq + (size_t)m * DD))[t] = ov;
}

// ===========================================================================
// Kernel 5: deterministic loss reduction (single block, fixed order)
// ===========================================================================
__global__ __launch_bounds__(256) void k_loss(float* __restrict__ out_loss) {
    __shared__ float s[256];
    float v = 0.f;
    for (int i = threadIdx.x; i < MM; i += 256) v += g_commit[i];
    s[threadIdx.x] = v;
    __syncthreads();
    for (int o = 128; o > 0; o >>= 1) {
        if (threadIdx.x < o) s[threadIdx.x] += s[threadIdx.x + o];
        __syncthreads();
    }
    if (threadIdx.x == 0) out_loss[0] = s[0] / (float)MM;
}

// ===========================================================================
extern "C" void kernel_launch(void* const* d_in, const int* in_sizes, int n_in,
                              void* d_out, int out_size) {
    const float* x  = (const float*)d_in[0];   // [8,2048,512]
    const float* cb = (const float*)d_in[1];   // [4096,512]
    const float* Wm = (const float*)d_in[2];   // [512,512]
    float* out = (float*)d_out;

    // layout: [quantized (M*D)] [indices (M)] [loss (1)]
    int idx_off  = out_size - MM - 1;
    int loss_off = out_size - 1;

    k_implicit<<<dim3(CC / 128, DD / 128), 256>>>(cb, Wm);
    k_halfnorm<<<CC / 8, 256>>>();
    k_argmin<<<MM / 128, 256>>>(x, out + idx_off);
    k_rot<<<MM, 128>>>(x, out);
    k_loss<<<1, 256>>>(out + loss_off);
}

// round 4
// speedup vs baseline: 2.5568x; 2.5568x over previous
#include <cuda_runtime.h>
#include <cuda_fp16.h>
#include <cstdint>

#define BB 8
#define NN 2048
#define DD 512
#define CC 4096
#define MM (BB*NN)   // 16384

// mma-kernel tiling
#define Bb_M 128
#define Bb_N 128
#define Bb_K 32
#define NCT (CC/Bb_N)         // 32 c-tiles
#define NKC (DD/Bb_K)         // 16 k-chunks
#define NQ  (NCT*NKC)         // 512 chunks
#define TPAD 8
#define TSTR 40               // halfs per row (32+8)
#define TILE_BYTES (128*TSTR*2)    // 10240
#define STAGE_BYTES (4*TILE_BYTES) // 40960 (A0,A1,B0,B1)
#define SMEM_DYN (2*STAGE_BYTES)   // 81920

// ---------------- scratch ----------------
__device__ float g_implicit[CC * DD];
__device__ float g_halfnorm[CC];
__device__ int   g_idx[MM];
__device__ float g_commit[MM];
__device__ __half g_xl0[MM * DD];
__device__ __half g_xl1[MM * DD];
__device__ __half g_cl0[CC * DD];
__device__ __half g_cl1[CC * DD];

// =============================== helpers ===================================
__device__ __forceinline__ uint32_t smem_u32(const void* p) {
    return (uint32_t)__cvta_generic_to_shared(p);
}
__device__ __forceinline__ void cp16(uint32_t s, const void* g) {
    asm volatile("cp.async.cg.shared.global [%0], [%1], 16;" :: "r"(s), "l"(g));
}
#define CP_COMMIT() asm volatile("cp.async.commit_group;")
#define CP_WAIT1()  asm volatile("cp.async.wait_group 1;")
#define CP_WAIT0()  asm volatile("cp.async.wait_group 0;")
#define LDM4(r0,r1,r2,r3,addr) \
    asm volatile("ldmatrix.sync.aligned.m8n8.x4.shared.b16 {%0,%1,%2,%3},[%4];" \
                 : "=r"(r0),"=r"(r1),"=r"(r2),"=r"(r3) : "r"(addr))
#define MMA16816(c,a,b) \
    asm volatile("mma.sync.aligned.m16n8k16.row.col.f32.f16.f16.f32 " \
                 "{%0,%1,%2,%3},{%4,%5,%6,%7},{%8,%9},{%0,%1,%2,%3};" \
                 : "+f"((c)[0]),"+f"((c)[1]),"+f"((c)[2]),"+f"((c)[3]) \
                 : "r"((a)[0]),"r"((a)[1]),"r"((a)[2]),"r"((a)[3]), \
                   "r"((b)[0]),"r"((b)[1]))

// ===========================================================================
// Kernel 1: implicit = codebook @ W^T  (fp32 SIMT, 2.1 GFLOP)
// ===========================================================================
__global__ __launch_bounds__(256) void k_implicit(const float* __restrict__ A,
                                                  const float* __restrict__ Wm) {
    __shared__ float As[8][128];
    __shared__ float Bs[8][128];
    const int tid = threadIdx.x;
    const int tx = tid & 15, ty = tid >> 4;
    const int m0 = blockIdx.x * 128;
    const int n0 = blockIdx.y * 128;
    const int lr = tid >> 1;
    const int lk = (tid & 1) * 4;

    float acc[2][2][4][4];
#pragma unroll
    for (int a = 0; a < 2; a++)
#pragma unroll
        for (int b = 0; b < 2; b++)
#pragma unroll
            for (int i = 0; i < 4; i++)
#pragma unroll
                for (int j = 0; j < 4; j++) acc[a][b][i][j] = 0.f;

    for (int k0 = 0; k0 < DD; k0 += 8) {
        float4 av = *(const float4*)&A[(size_t)(m0 + lr) * DD + k0 + lk];
        float4 bv = *(const float4*)&Wm[(size_t)(n0 + lr) * DD + k0 + lk];
        __syncthreads();
        As[lk + 0][lr] = av.x; As[lk + 1][lr] = av.y; As[lk + 2][lr] = av.z; As[lk + 3][lr] = av.w;
        Bs[lk + 0][lr] = bv.x; Bs[lk + 1][lr] = bv.y; Bs[lk + 2][lr] = bv.z; Bs[lk + 3][lr] = bv.w;
        __syncthreads();
#pragma unroll
        for (int kk = 0; kk < 8; kk++) {
            float4 a0 = *(const float4*)&As[kk][ty * 4];
            float4 a1 = *(const float4*)&As[kk][64 + ty * 4];
            float4 b0 = *(const float4*)&Bs[kk][tx * 4];
            float4 b1 = *(const float4*)&Bs[kk][64 + tx * 4];
            float ar[8] = {a0.x, a0.y, a0.z, a0.w, a1.x, a1.y, a1.z, a1.w};
            float br[8] = {b0.x, b0.y, b0.z, b0.w, b1.x, b1.y, b1.z, b1.w};
#pragma unroll
            for (int ih = 0; ih < 2; ih++)
#pragma unroll
                for (int i = 0; i < 4; i++)
#pragma unroll
                    for (int jh = 0; jh < 2; jh++)
#pragma unroll
                        for (int j = 0; j < 4; j++)
                            acc[ih][jh][i][j] += ar[ih * 4 + i] * br[jh * 4 + j];
        }
    }
#pragma unroll
    for (int ih = 0; ih < 2; ih++)
#pragma unroll
        for (int i = 0; i < 4; i++) {
            int rm = m0 + ih * 64 + ty * 4 + i;
#pragma unroll
            for (int jh = 0; jh < 2; jh++) {
                int cn = n0 + jh * 64 + tx * 4;
                float4 v = make_float4(acc[ih][jh][i][0], acc[ih][jh][i][1],
                                       acc[ih][jh][i][2], acc[ih][jh][i][3]);
                *(float4*)&g_implicit[(size_t)rm * DD + cn] = v;
            }
        }
}

// ===========================================================================
// Kernel 2: 2-limb fp16 split:  v = h0 + h1 + O(2^-22 v)
// ===========================================================================
__global__ __launch_bounds__(256) void k_split2(const float* __restrict__ src,
                                                __half* __restrict__ d0,
                                                __half* __restrict__ d1, int n) {
    int i = 4 * (blockIdx.x * 256 + threadIdx.x);
    if (i >= n) return;
    float4 v = *(const float4*)(src + i);
    float vv[4] = {v.x, v.y, v.z, v.w};
    __half L0[4], L1[4];
#pragma unroll
    for (int c = 0; c < 4; c++) {
        __half h0 = __float2half_rn(vv[c]);
        float r = vv[c] - __half2float(h0);
        L0[c] = h0;
        L1[c] = __float2half_rn(r);
    }
    *(uint2*)(d0 + i) = *(uint2*)L0;
    *(uint2*)(d1 + i) = *(uint2*)L1;
}

// ===========================================================================
// Kernel 3: halfnorm[c] = 0.5 * ||implicit[c]||^2
// ===========================================================================
__global__ __launch_bounds__(256) void k_halfnorm() {
    int warp = threadIdx.x >> 5, lane = threadIdx.x & 31;
    int row = blockIdx.x * 8 + warp;
    const float* p = g_implicit + (size_t)row * DD;
    float s = 0.f;
#pragma unroll
    for (int k = 0; k < DD / 32; k++) {
        float v = p[lane + 32 * k];
        s += v * v;
    }
#pragma unroll
    for (int o = 16; o > 0; o >>= 1) s += __shfl_xor_sync(0xffffffff, s, o);
    if (lane == 0) g_halfnorm[row] = 0.5f * s;
}

// ===========================================================================
// Kernel 4: HMMA fused score-GEMM + argmin.
// dot(x_m, imp_c) via fp16 2-limb 3-product; score = 0.5||imp_c||^2 - dot.
// CTA 128x128 tile over M; loops 32 c-tiles, cp.async double-buffered k=32.
// ===========================================================================
__device__ __forceinline__ void issue_chunk(uint32_t st, int m0, int ct, int kc, int tid) {
    const __half* gp0 = g_xl0; const __half* gp1 = g_xl1;
    const __half* gp2 = g_cl0; const __half* gp3 = g_cl1;
    int c0 = ct * Bb_N;
#pragma unroll
    for (int j = 0; j < 2; j++) {
        int seg = tid * 2 + j;         // 0..511
        int r = seg >> 2, s = seg & 3;
        uint32_t so = r * (TSTR * 2) + s * 16;
        size_t go = (size_t)r * DD + kc * Bb_K + s * 8;
        cp16(st + 0 * TILE_BYTES + so, gp0 + (size_t)m0 * DD + go);
        cp16(st + 1 * TILE_BYTES + so, gp1 + (size_t)m0 * DD + go);
        cp16(st + 2 * TILE_BYTES + so, gp2 + (size_t)c0 * DD + go);
        cp16(st + 3 * TILE_BYTES + so, gp3 + (size_t)c0 * DD + go);
    }
}

__global__ __launch_bounds__(256, 1) void k_argmin_mma(float* __restrict__ out_idx_f) {
    extern __shared__ char dsm[];
    __shared__ float redv[4][128];
    __shared__ int   redi[4][128];

    const uint32_t sb = smem_u32(dsm);
    const int tid = threadIdx.x;
    const int lane = tid & 31;
    const int wid = tid >> 5;
    const int warp_m = wid >> 2;      // 0..1
    const int warp_n = wid & 3;       // 0..3
    const int m0 = blockIdx.x * Bb_M;
    const int gID = lane >> 2;        // 0..7
    const int tg  = lane & 3;         // 0..3

    // ldmatrix per-thread base offsets (bytes)
    const uint32_t aOff = (uint32_t)(warp_m * 64 + (lane & 15)) * (TSTR * 2)
                        + ((lane >> 4) << 4);
    const uint32_t bOff = (uint32_t)(warp_n * 32 + ((lane >> 4) & 1) * 8 + (lane & 7)) * (TSTR * 2)
                        + (((lane >> 3) & 1) << 4);

    float bestv = 3.4e38f;
    int   besti = 0;

    float acc[4][4][4];

    // prologue: chunk 0
    issue_chunk(sb, m0, 0, 0, tid);
    CP_COMMIT();

    for (int q = 0; q < NQ; q++) {
        const int ct = q >> 4;
        const int kc = q & 15;
        if (q + 1 < NQ) {
            int qn = q + 1;
            issue_chunk(sb + (qn & 1) * STAGE_BYTES, m0, qn >> 4, qn & 15, tid);
            CP_COMMIT();
            CP_WAIT1();
        } else {
            CP_WAIT0();
        }
        __syncthreads();

        if (kc == 0) {
#pragma unroll
            for (int mt = 0; mt < 4; mt++)
#pragma unroll
                for (int nt = 0; nt < 4; nt++)
#pragma unroll
                    for (int e = 0; e < 4; e++) acc[mt][nt][e] = 0.f;
        }

        const uint32_t st = sb + (q & 1) * STAGE_BYTES;
#pragma unroll
        for (int ks = 0; ks < 2; ks++) {
            uint32_t aF[4][4], b0F[4][2], b1F[4][2];
            // A limb0 fragments
#pragma unroll
            for (int mt = 0; mt < 4; mt++)
                LDM4(aF[mt][0], aF[mt][1], aF[mt][2], aF[mt][3],
                     st + 0 * TILE_BYTES + aOff + mt * (16 * TSTR * 2) + ks * 32);
            // B limb0 fragments
#pragma unroll
            for (int p = 0; p < 2; p++) {
                uint32_t r0, r1, r2, r3;
                LDM4(r0, r1, r2, r3,
                     st + 2 * TILE_BYTES + bOff + p * (16 * TSTR * 2) + ks * 32);
                b0F[2 * p][0] = r0; b0F[2 * p][1] = r1;
                b0F[2 * p + 1][0] = r2; b0F[2 * p + 1][1] = r3;
            }
#pragma unroll
            for (int mt = 0; mt < 4; mt++)
#pragma unroll
                for (int nt = 0; nt < 4; nt++) MMA16816(acc[mt][nt], aF[mt], b0F[nt]);
            // B limb1
#pragma unroll
            for (int p = 0; p < 2; p++) {
                uint32_t r0, r1, r2, r3;
                LDM4(r0, r1, r2, r3,
                     st + 3 * TILE_BYTES + bOff + p * (16 * TSTR * 2) + ks * 32);
                b1F[2 * p][0] = r0; b1F[2 * p][1] = r1;
                b1F[2 * p + 1][0] = r2; b1F[2 * p + 1][1] = r3;
            }
#pragma unroll
            for (int mt = 0; mt < 4; mt++)
#pragma unroll
                for (int nt = 0; nt < 4; nt++) MMA16816(acc[mt][nt], aF[mt], b1F[nt]);
            // A limb1
#pragma unroll
            for (int mt = 0; mt < 4; mt++)
                LDM4(aF[mt][0], aF[mt][1], aF[mt][2], aF[mt][3],
                     st + 1 * TILE_BYTES + aOff + mt * (16 * TSTR * 2) + ks * 32);
#pragma unroll
            for (int mt = 0; mt < 4; mt++)
#pragma unroll
                for (int nt = 0; nt < 4; nt++) MMA16816(acc[mt][nt], aF[mt], b0F[nt]);
        }
        __syncthreads();   // stage consumed; safe to overwrite next iter

        if (kc == 15) {
            // -------- argmin epilogue for this c-tile --------
#pragma unroll
            for (int mt = 0; mt < 4; mt++) {
#pragma unroll
                for (int half = 0; half < 2; half++) {
                    float v = 3.4e38f; int vi = 0;
#pragma unroll
                    for (int nt = 0; nt < 4; nt++) {
#pragma unroll
                        for (int j = 0; j < 2; j++) {
                            int c = ct * Bb_N + warp_n * 32 + nt * 8 + tg * 2 + j;
                            float s = __ldg(&g_halfnorm[c]) - acc[mt][nt][2 * half + j];
                            if (s < v) { v = s; vi = c; }
                        }
                    }
#pragma unroll
                    for (int off = 1; off <= 2; off <<= 1) {
                        float ov = __shfl_xor_sync(0xffffffff, v, off);
                        int   oi = __shfl_xor_sync(0xffffffff, vi, off);
                        if (ov < v || (ov == v && oi < vi)) { v = ov; vi = oi; }
                    }
                    if (tg == 0) {
                        int r = warp_m * 64 + mt * 16 + gID + 8 * half;
                        redv[warp_n][r] = v;
                        redi[warp_n][r] = vi;
                    }
                }
            }
            __syncthreads();
            if (tid < 128) {
#pragma unroll
                for (int wn = 0; wn < 4; wn++) {
                    float ov = redv[wn][tid]; int oi = redi[wn][tid];
                    if (ov < bestv || (ov == bestv && oi < besti)) { bestv = ov; besti = oi; }
                }
            }
            __syncthreads();
        }
    }

    if (tid < 128) {
        int gm = m0 + tid;
        g_idx[gm] = besti;
        out_idx_f[gm] = (float)besti;
    }
}

// ===========================================================================
// Kernel 5: rotation trick + per-row commit sum. One block per x-row.
// ===========================================================================
__global__ __launch_bounds__(128) void k_rot(const float* __restrict__ X,
                                             float* __restrict__ outq) {
    __shared__ float red[4][4];
    const int m = blockIdx.x;
    const int t = threadIdx.x;
    const float* xr = X + (size_t)m * DD;
    const float* qr = g_implicit + (size_t)g_idx[m] * DD;

    float4 xv = ((const float4*)xr)[t];
    float4 qv = ((const float4*)qr)[t];

    float sx  = xv.x * xv.x + xv.y * xv.y + xv.z * xv.z + xv.w * xv.w;
    float sq  = qv.x * qv.x + qv.y * qv.y + qv.z * qv.z + qv.w * qv.w;
    float sxq = xv.x * qv.x + xv.y * qv.y + xv.z * qv.z + xv.w * qv.w;
    float d0 = xv.x - qv.x + 1e-6f, d1 = xv.y - qv.y + 1e-6f;
    float d2 = xv.z - qv.z + 1e-6f, d3 = xv.w - qv.w + 1e-6f;
    float sc = d0 * d0 + d1 * d1 + d2 * d2 + d3 * d3;

#pragma unroll
    for (int o = 16; o > 0; o >>= 1) {
        sx  += __shfl_xor_sync(0xffffffff, sx, o);
        sq  += __shfl_xor_sync(0xffffffff, sq, o);
        sxq += __shfl_xor_sync(0xffffffff, sxq, o);
        sc  += __shfl_xor_sync(0xffffffff, sc, o);
    }
    int warp = t >> 5, lane = t & 31;
    if (lane == 0) { red[warp][0] = sx; red[warp][1] = sq; red[warp][2] = sxq; red[warp][3] = sc; }
    __syncthreads();
    sx  = red[0][0] + red[1][0] + red[2][0] + red[3][0];
    sq  = red[0][1] + red[1][1] + red[2][1] + red[3][1];
    sxq = red[0][2] + red[1][2] + red[2][2] + red[3][2];
    sc  = red[0][3] + red[1][3] + red[2][3] + red[3][3];

    if (t == 0) g_commit[m] = sc;

    float norm_x = sqrtf(sx), norm_q = sqrtf(sq);
    float nx = fmaxf(norm_x, 1e-6f);
    float nq = fmaxf(norm_q, 1e-6f);
    float uq2 = sx / (nx * nx) + sq / (nq * nq) + 2.f * sxq / (nx * nq);
    float nuq = sqrtf(fmaxf(uq2, 0.f));
    float wden = fmaxf(nuq, 1e-12f);
    float e_w = (sx / nx + sxq / nq) / wden;
    float e_u = sx / nx;
    float c1 = 2.f * e_w / wden;
    float c2 = 2.f * e_u;
    float scale = norm_q / nx;
    float coef_x = (1.f - c1 / nx) * scale;
    float coef_q = ((c2 - c1) / nq) * scale;

    float4 ov;
    ov.x = coef_x * xv.x + coef_q * qv.x;
    ov.y = coef_x * xv.y + coef_q * qv.y;
    ov.z = coef_x * xv.z + coef_q * qv.z;
    ov.w = coef_x * xv.w + coef_q * qv.w;
    ((float4*)(outq + (size_t)m * DD))[t] = ov;
}

// ===========================================================================
// Kernel 6: deterministic loss reduction
// ===========================================================================
__global__ __launch_bounds__(256) void k_loss(float* __restrict__ out_loss) {
    __shared__ float s[256];
    float v = 0.f;
    for (int i = threadIdx.x; i < MM; i += 256) v += g_commit[i];
    s[threadIdx.x] = v;
    __syncthreads();
    for (int o = 128; o > 0; o >>= 1) {
        if (threadIdx.x < o) s[threadIdx.x] += s[threadIdx.x + o];
        __syncthreads();
    }
    if (threadIdx.x == 0) out_loss[0] = s[0] / (float)MM;
}

// ===========================================================================
extern "C" void kernel_launch(void* const* d_in, const int* in_sizes, int n_in,
                              void* d_out, int out_size) {
    const float* x  = (const float*)d_in[0];
    const float* cb = (const float*)d_in[1];
    const float* Wm = (const float*)d_in[2];
    float* out = (float*)d_out;

    int idx_off  = out_size - MM - 1;
    int loss_off = out_size - 1;

    static bool attr_done = false;
    if (!attr_done) {
        cudaFuncSetAttribute(k_argmin_mma, cudaFuncAttributeMaxDynamicSharedMemorySize, SMEM_DYN);
        attr_done = true;
    }

    __half *xl0, *xl1, *cl0, *cl1; float* imp;
    cudaGetSymbolAddress((void**)&xl0, g_xl0);
    cudaGetSymbolAddress((void**)&xl1, g_xl1);
    cudaGetSymbolAddress((void**)&cl0, g_cl0);
    cudaGetSymbolAddress((void**)&cl1, g_cl1);
    cudaGetSymbolAddress((void**)&imp, g_implicit);

    k_implicit<<<dim3(CC / 128, DD / 128), 256>>>(cb, Wm);
    k_split2<<<(MM * DD / 4 + 255) / 256, 256>>>(x, xl0, xl1, MM * DD);
    k_split2<<<(CC * DD / 4 + 255) / 256, 256>>>(imp, cl0, cl1, CC * DD);
    k_halfnorm<<<CC / 8, 256>>>();
    k_argmin_mma<<<MM / Bb_M, 256, SMEM_DYN>>>(out + idx_off);
    k_rot<<<MM, 128>>>(x, out);
    k_loss<<<1, 256>>>(out + loss_off);
}

// round 5
// speedup vs baseline: 2.6373x; 1.0315x over previous
#include <cuda_runtime.h>
#include <cuda_fp16.h>
#include <cstdint>

#define BB 8
#define NN 2048
#define DD 512
#define CC 4096
#define MM (BB*NN)   // 16384

// mma-kernel tiling
#define Bb_M 128
#define Bb_N 128
#define Bb_K 32
#define NCT (CC/Bb_N)         // 32 c-tiles
#define NKC (DD/Bb_K)         // 16 k-chunks
#define NQ  (NCT*NKC)         // 512 chunks
#define TSTR 40               // halfs per row (32+8 pad)
#define TILE_BYTES (128*TSTR*2)    // 10240
#define STAGE_BYTES (4*TILE_BYTES) // 40960 (A0,A1,B0,B1)
#define NSTAGE 4
#define SMEM_DYN (NSTAGE*STAGE_BYTES)  // 163840

// ---------------- scratch ----------------
__device__ float g_implicit[CC * DD];
__device__ float g_halfnorm[CC];
__device__ int   g_idx[MM];
__device__ float g_commit[MM];
__device__ __half g_xl0[MM * DD];
__device__ __half g_xl1[MM * DD];
__device__ __half g_cl0[CC * DD];
__device__ __half g_cl1[CC * DD];

// =============================== helpers ===================================
__device__ __forceinline__ uint32_t smem_u32(const void* p) {
    return (uint32_t)__cvta_generic_to_shared(p);
}
__device__ __forceinline__ void cp16(uint32_t s, const void* g) {
    asm volatile("cp.async.cg.shared.global [%0], [%1], 16;" :: "r"(s), "l"(g));
}
#define CP_COMMIT() asm volatile("cp.async.commit_group;")
#define CP_WAIT2()  asm volatile("cp.async.wait_group 2;")
#define CP_WAIT0()  asm volatile("cp.async.wait_group 0;")
#define LDM4(r0,r1,r2,r3,addr) \
    asm volatile("ldmatrix.sync.aligned.m8n8.x4.shared.b16 {%0,%1,%2,%3},[%4];" \
                 : "=r"(r0),"=r"(r1),"=r"(r2),"=r"(r3) : "r"(addr))
#define MMA16816(c,a,b) \
    asm volatile("mma.sync.aligned.m16n8k16.row.col.f32.f16.f16.f32 " \
                 "{%0,%1,%2,%3},{%4,%5,%6,%7},{%8,%9},{%0,%1,%2,%3};" \
                 : "+f"((c)[0]),"+f"((c)[1]),"+f"((c)[2]),"+f"((c)[3]) \
                 : "r"((a)[0]),"r"((a)[1]),"r"((a)[2]),"r"((a)[3]), \
                   "r"((b)[0]),"r"((b)[1]))

// ===========================================================================
// Kernel 1: implicit = codebook @ W^T  (fp32 SIMT, 2.1 GFLOP)
// ===========================================================================
__global__ __launch_bounds__(256) void k_implicit(const float* __restrict__ A,
                                                  const float* __restrict__ Wm) {
    __shared__ float As[8][128];
    __shared__ float Bs[8][128];
    const int tid = threadIdx.x;
    const int tx = tid & 15, ty = tid >> 4;
    const int m0 = blockIdx.x * 128;
    const int n0 = blockIdx.y * 128;
    const int lr = tid >> 1;
    const int lk = (tid & 1) * 4;

    float acc[2][2][4][4];
#pragma unroll
    for (int a = 0; a < 2; a++)
#pragma unroll
        for (int b = 0; b < 2; b++)
#pragma unroll
            for (int i = 0; i < 4; i++)
#pragma unroll
                for (int j = 0; j < 4; j++) acc[a][b][i][j] = 0.f;

    for (int k0 = 0; k0 < DD; k0 += 8) {
        float4 av = *(const float4*)&A[(size_t)(m0 + lr) * DD + k0 + lk];
        float4 bv = *(const float4*)&Wm[(size_t)(n0 + lr) * DD + k0 + lk];
        __syncthreads();
        As[lk + 0][lr] = av.x; As[lk + 1][lr] = av.y; As[lk + 2][lr] = av.z; As[lk + 3][lr] = av.w;
        Bs[lk + 0][lr] = bv.x; Bs[lk + 1][lr] = bv.y; Bs[lk + 2][lr] = bv.z; Bs[lk + 3][lr] = bv.w;
        __syncthreads();
#pragma unroll
        for (int kk = 0; kk < 8; kk++) {
            float4 a0 = *(const float4*)&As[kk][ty * 4];
            float4 a1 = *(const float4*)&As[kk][64 + ty * 4];
            float4 b0 = *(const float4*)&Bs[kk][tx * 4];
            float4 b1 = *(const float4*)&Bs[kk][64 + tx * 4];
            float ar[8] = {a0.x, a0.y, a0.z, a0.w, a1.x, a1.y, a1.z, a1.w};
            float br[8] = {b0.x, b0.y, b0.z, b0.w, b1.x, b1.y, b1.z, b1.w};
#pragma unroll
            for (int ih = 0; ih < 2; ih++)
#pragma unroll
                for (int i = 0; i < 4; i++)
#pragma unroll
                    for (int jh = 0; jh < 2; jh++)
#pragma unroll
                        for (int j = 0; j < 4; j++)
                            acc[ih][jh][i][j] += ar[ih * 4 + i] * br[jh * 4 + j];
        }
    }
#pragma unroll
    for (int ih = 0; ih < 2; ih++)
#pragma unroll
        for (int i = 0; i < 4; i++) {
            int rm = m0 + ih * 64 + ty * 4 + i;
#pragma unroll
            for (int jh = 0; jh < 2; jh++) {
                int cn = n0 + jh * 64 + tx * 4;
                float4 v = make_float4(acc[ih][jh][i][0], acc[ih][jh][i][1],
                                       acc[ih][jh][i][2], acc[ih][jh][i][3]);
                *(float4*)&g_implicit[(size_t)rm * DD + cn] = v;
            }
        }
}

// ===========================================================================
// Kernel 2: 2-limb fp16 split:  v = h0 + h1 + O(2^-22 v)
// ===========================================================================
__global__ __launch_bounds__(256) void k_split2(const float* __restrict__ src,
                                                __half* __restrict__ d0,
                                                __half* __restrict__ d1, int n) {
    int i = 4 * (blockIdx.x * 256 + threadIdx.x);
    if (i >= n) return;
    float4 v = *(const float4*)(src + i);
    float vv[4] = {v.x, v.y, v.z, v.w};
    __half L0[4], L1[4];
#pragma unroll
    for (int c = 0; c < 4; c++) {
        __half h0 = __float2half_rn(vv[c]);
        float r = vv[c] - __half2float(h0);
        L0[c] = h0;
        L1[c] = __float2half_rn(r);
    }
    *(uint2*)(d0 + i) = *(uint2*)L0;
    *(uint2*)(d1 + i) = *(uint2*)L1;
}

// ===========================================================================
// Kernel 3: halfnorm[c] = 0.5 * ||implicit[c]||^2
// ===========================================================================
__global__ __launch_bounds__(256) void k_halfnorm() {
    int warp = threadIdx.x >> 5, lane = threadIdx.x & 31;
    int row = blockIdx.x * 8 + warp;
    const float* p = g_implicit + (size_t)row * DD;
    float s = 0.f;
#pragma unroll
    for (int k = 0; k < DD / 32; k++) {
        float v = p[lane + 32 * k];
        s += v * v;
    }
#pragma unroll
    for (int o = 16; o > 0; o >>= 1) s += __shfl_xor_sync(0xffffffff, s, o);
    if (lane == 0) g_halfnorm[row] = 0.5f * s;
}

// ===========================================================================
// Kernel 4: HMMA fused score-GEMM + argmin, 4-stage cp.async pipeline.
// ===========================================================================
__device__ __forceinline__ void issue_chunk(uint32_t st, int m0, int ct, int kc, int tid) {
    const __half* gp0 = g_xl0; const __half* gp1 = g_xl1;
    const __half* gp2 = g_cl0; const __half* gp3 = g_cl1;
    int c0 = ct * Bb_N;
#pragma unroll
    for (int j = 0; j < 2; j++) {
        int seg = tid * 2 + j;         // 0..511
        int r = seg >> 2, s = seg & 3;
        uint32_t so = r * (TSTR * 2) + s * 16;
        size_t go = (size_t)r * DD + kc * Bb_K + s * 8;
        cp16(st + 0 * TILE_BYTES + so, gp0 + (size_t)m0 * DD + go);
        cp16(st + 1 * TILE_BYTES + so, gp1 + (size_t)m0 * DD + go);
        cp16(st + 2 * TILE_BYTES + so, gp2 + (size_t)c0 * DD + go);
        cp16(st + 3 * TILE_BYTES + so, gp3 + (size_t)c0 * DD + go);
    }
}

__global__ __launch_bounds__(256, 1) void k_argmin_mma(float* __restrict__ out_idx_f) {
    extern __shared__ char dsm[];
    __shared__ float redv[4][128];
    __shared__ int   redi[4][128];

    const uint32_t sb = smem_u32(dsm);
    const int tid = threadIdx.x;
    const int lane = tid & 31;
    const int wid = tid >> 5;
    const int warp_m = wid >> 2;      // 0..1
    const int warp_n = wid & 3;       // 0..3
    const int m0 = blockIdx.x * Bb_M;
    const int gID = lane >> 2;        // 0..7
    const int tg  = lane & 3;         // 0..3

    const uint32_t aOff = (uint32_t)(warp_m * 64 + (lane & 15)) * (TSTR * 2)
                        + ((lane >> 4) << 4);
    const uint32_t bOff = (uint32_t)(warp_n * 32 + ((lane >> 4) & 1) * 8 + (lane & 7)) * (TSTR * 2)
                        + (((lane >> 3) & 1) << 4);

    float bestv = 3.4e38f;
    int   besti = 0;
    float acc[4][4][4];

    // prologue: stages 0..2
    issue_chunk(sb + 0 * STAGE_BYTES, m0, 0, 0, tid); CP_COMMIT();
    issue_chunk(sb + 1 * STAGE_BYTES, m0, 0, 1, tid); CP_COMMIT();
    issue_chunk(sb + 2 * STAGE_BYTES, m0, 0, 2, tid); CP_COMMIT();

    for (int q = 0; q < NQ; q++) {
        const int ct = q >> 4;
        const int kc = q & 15;

        CP_WAIT2();          // chunk q resident; q+1,q+2 in flight
        __syncthreads();     // all warps done with buffer (q-1)&3 (=(q+3)&3)

        const int qn = q + 3;
        if (qn < NQ)
            issue_chunk(sb + (qn & 3) * STAGE_BYTES, m0, qn >> 4, qn & 15, tid);
        CP_COMMIT();

        if (kc == 0) {
#pragma unroll
            for (int mt = 0; mt < 4; mt++)
#pragma unroll
                for (int nt = 0; nt < 4; nt++)
#pragma unroll
                    for (int e = 0; e < 4; e++) acc[mt][nt][e] = 0.f;
        }

        const uint32_t st = sb + (q & 3) * STAGE_BYTES;
#pragma unroll
        for (int ks = 0; ks < 2; ks++) {
            uint32_t aF[4][4], b0F[4][2], b1F[4][2];
#pragma unroll
            for (int mt = 0; mt < 4; mt++)
                LDM4(aF[mt][0], aF[mt][1], aF[mt][2], aF[mt][3],
                     st + 0 * TILE_BYTES + aOff + mt * (16 * TSTR * 2) + ks * 32);
#pragma unroll
            for (int p = 0; p < 2; p++) {
                uint32_t r0, r1, r2, r3;
                LDM4(r0, r1, r2, r3,
                     st + 2 * TILE_BYTES + bOff + p * (16 * TSTR * 2) + ks * 32);
                b0F[2 * p][0] = r0; b0F[2 * p][1] = r1;
                b0F[2 * p + 1][0] = r2; b0F[2 * p + 1][1] = r3;
            }
#pragma unroll
            for (int mt = 0; mt < 4; mt++)
#pragma unroll
                for (int nt = 0; nt < 4; nt++) MMA16816(acc[mt][nt], aF[mt], b0F[nt]);
#pragma unroll
            for (int p = 0; p < 2; p++) {
                uint32_t r0, r1, r2, r3;
                LDM4(r0, r1, r2, r3,
                     st + 3 * TILE_BYTES + bOff + p * (16 * TSTR * 2) + ks * 32);
                b1F[2 * p][0] = r0; b1F[2 * p][1] = r1;
                b1F[2 * p + 1][0] = r2; b1F[2 * p + 1][1] = r3;
            }
#pragma unroll
            for (int mt = 0; mt < 4; mt++)
#pragma unroll
                for (int nt = 0; nt < 4; nt++) MMA16816(acc[mt][nt], aF[mt], b1F[nt]);
#pragma unroll
            for (int mt = 0; mt < 4; mt++)
                LDM4(aF[mt][0], aF[mt][1], aF[mt][2], aF[mt][3],
                     st + 1 * TILE_BYTES + aOff + mt * (16 * TSTR * 2) + ks * 32);
#pragma unroll
            for (int mt = 0; mt < 4; mt++)
#pragma unroll
                for (int nt = 0; nt < 4; nt++) MMA16816(acc[mt][nt], aF[mt], b0F[nt]);
        }

        if (kc == 15) {
            // -------- argmin epilogue for this c-tile --------
#pragma unroll
            for (int mt = 0; mt < 4; mt++) {
#pragma unroll
                for (int half = 0; half < 2; half++) {
                    float v = 3.4e38f; int vi = 0;
#pragma unroll
                    for (int nt = 0; nt < 4; nt++) {
#pragma unroll
                        for (int j = 0; j < 2; j++) {
                            int c = ct * Bb_N + warp_n * 32 + nt * 8 + tg * 2 + j;
                            float s = __ldg(&g_halfnorm[c]) - acc[mt][nt][2 * half + j];
                            if (s < v) { v = s; vi = c; }
                        }
                    }
#pragma unroll
                    for (int off = 1; off <= 2; off <<= 1) {
                        float ov = __shfl_xor_sync(0xffffffff, v, off);
                        int   oi = __shfl_xor_sync(0xffffffff, vi, off);
                        if (ov < v || (ov == v && oi < vi)) { v = ov; vi = oi; }
                    }
                    if (tg == 0) {
                        int r = warp_m * 64 + mt * 16 + gID + 8 * half;
                        redv[warp_n][r] = v;
                        redi[warp_n][r] = vi;
                    }
                }
            }
            __syncthreads();
            if (tid < 128) {
#pragma unroll
                for (int wn = 0; wn < 4; wn++) {
                    float ov = redv[wn][tid]; int oi = redi[wn][tid];
                    if (ov < bestv || (ov == bestv && oi < besti)) { bestv = ov; besti = oi; }
                }
            }
            __syncthreads();
        }
    }

    if (tid < 128) {
        int gm = m0 + tid;
        g_idx[gm] = besti;
        out_idx_f[gm] = (float)besti;
    }
}

// ===========================================================================
// Kernel 5: rotation trick + per-row commit sum. One block per x-row.
// ===========================================================================
__global__ __launch_bounds__(128) void k_rot(const float* __restrict__ X,
                                             float* __restrict__ outq) {
    __shared__ float red[4][4];
    const int m = blockIdx.x;
    const int t = threadIdx.x;
    const float* xr = X + (size_t)m * DD;
    const float* qr = g_implicit + (size_t)g_idx[m] * DD;

    float4 xv = ((const float4*)xr)[t];
    float4 qv = ((const float4*)qr)[t];

    float sx  = xv.x * xv.x + xv.y * xv.y + xv.z * xv.z + xv.w * xv.w;
    float sq  = qv.x * qv.x + qv.y * qv.y + qv.z * qv.z + qv.w * qv.w;
    float sxq = xv.x * qv.x + xv.y * qv.y + xv.z * qv.z + xv.w * qv.w;
    float d0 = xv.x - qv.x + 1e-6f, d1 = xv.y - qv.y + 1e-6f;
    float d2 = xv.z - qv.z + 1e-6f, d3 = xv.w - qv.w + 1e-6f;
    float sc = d0 * d0 + d1 * d1 + d2 * d2 + d3 * d3;

#pragma unroll
    for (int o = 16; o > 0; o >>= 1) {
        sx  += __shfl_xor_sync(0xffffffff, sx, o);
        sq  += __shfl_xor_sync(0xffffffff, sq, o);
        sxq += __shfl_xor_sync(0xffffffff, sxq, o);
        sc  += __shfl_xor_sync(0xffffffff, sc, o);
    }
    int warp = t >> 5, lane = t & 31;
    if (lane == 0) { red[warp][0] = sx; red[warp][1] = sq; red[warp][2] = sxq; red[warp][3] = sc; }
    __syncthreads();
    sx  = red[0][0] + red[1][0] + red[2][0] + red[3][0];
    sq  = red[0][1] + red[1][1] + red[2][1] + red[3][1];
    sxq = red[0][2] + red[1][2] + red[2][2] + red[3][2];
    sc  = red[0][3] + red[1][3] + red[2][3] + red[3][3];

    if (t == 0) g_commit[m] = sc;

    float norm_x = sqrtf(sx), norm_q = sqrtf(sq);
    float nx = fmaxf(norm_x, 1e-6f);
    float nq = fmaxf(norm_q, 1e-6f);
    float uq2 = sx / (nx * nx) + sq / (nq * nq) + 2.f * sxq / (nx * nq);
    float nuq = sqrtf(fmaxf(uq2, 0.f));
    float wden = fmaxf(nuq, 1e-12f);
    float e_w = (sx / nx + sxq / nq) / wden;
    float e_u = sx / nx;
    float c1 = 2.f * e_w / wden;
    float c2 = 2.f * e_u;
    float scale = norm_q / nx;
    float coef_x = (1.f - c1 / nx) * scale;
    float coef_q = ((c2 - c1) / nq) * scale;

    float4 ov;
    ov.x = coef_x * xv.x + coef_q * qv.x;
    ov.y = coef_x * xv.y + coef_q * qv.y;
    ov.z = coef_x * xv.z + coef_q * qv.z;
    ov.w = coef_x * xv.w + coef_q * qv.w;
    ((float4*)(outq + (size_t)m * DD))[t] = ov;
}

// ===========================================================================
// Kernel 6: deterministic loss reduction
// ===========================================================================
__global__ __launch_bounds__(256) void k_loss(float* __restrict__ out_loss) {
    __shared__ float s[256];
    float v = 0.f;
    for (int i = threadIdx.x; i < MM; i += 256) v += g_commit[i];
    s[threadIdx.x] = v;
    __syncthreads();
    for (int o = 128; o > 0; o >>= 1) {
        if (threadIdx.x < o) s[threadIdx.x] += s[threadIdx.x + o];
        __syncthreads();
    }
    if (threadIdx.x == 0) out_loss[0] = s[0] / (float)MM;
}

// ===========================================================================
extern "C" void kernel_launch(void* const* d_in, const int* in_sizes, int n_in,
                              void* d_out, int out_size) {
    const float* x  = (const float*)d_in[0];
    const float* cb = (const float*)d_in[1];
    const float* Wm = (const float*)d_in[2];
    float* out = (float*)d_out;

    int idx_off  = out_size - MM - 1;
    int loss_off = out_size - 1;

    static bool attr_done = false;
    if (!attr_done) {
        cudaFuncSetAttribute(k_argmin_mma, cudaFuncAttributeMaxDynamicSharedMemorySize, SMEM_DYN);
        attr_done = true;
    }

    __half *xl0, *xl1, *cl0, *cl1; float* imp;
    cudaGetSymbolAddress((void**)&xl0, g_xl0);
    cudaGetSymbolAddress((void**)&xl1, g_xl1);
    cudaGetSymbolAddress((void**)&cl0, g_cl0);
    cudaGetSymbolAddress((void**)&cl1, g_cl1);
    cudaGetSymbolAddress((void**)&imp, g_implicit);

    k_implicit<<<dim3(CC / 128, DD / 128), 256>>>(cb, Wm);
    k_split2<<<(MM * DD / 4 + 255) / 256, 256>>>(x, xl0, xl1, MM * DD);
    k_split2<<<(CC * DD / 4 + 255) / 256, 256>>>(imp, cl0, cl1, CC * DD);
    k_halfnorm<<<CC / 8, 256>>>();
    k_argmin_mma<<<MM / Bb_M, 256, SMEM_DYN>>>(out + idx_off);
    k_rot<<<MM, 128>>>(x, out);
    k_loss<<<1, 256>>>(out + loss_off);
}

// round 6
// speedup vs baseline: 3.1556x; 1.1965x over previous
#include <cuda_runtime.h>
#include <cuda_fp16.h>
#include <cstdint>

#define BB 8
#define NN 2048
#define DD 512
#define CC 4096
#define MM (BB*NN)   // 16384

// mma-kernel tiling
#define Bb_M 128
#define Bb_N 128
#define Bb_K 32
#define NCT (CC/Bb_N)         // 32 c-tiles
#define NKC (DD/Bb_K)         // 16 k-chunks
#define NQ  (NCT*NKC)         // 512 chunks
#define TSTR 40               // halfs per row (32+8 pad)
#define TILE_BYTES (128*TSTR*2)    // 10240
#define STAGE_BYTES (2*TILE_BYTES) // 20480 (A0, B0)
#define NSTAGE 4
#define SMEM_DYN (NSTAGE*STAGE_BYTES)  // 81920

// ---------------- scratch ----------------
__device__ float g_implicit[CC * DD];
__device__ float g_halfnorm[CC];
__device__ int   g_idx[MM];
__device__ int   g_cand[MM * 4];
__device__ float g_commit[MM];
__device__ __half g_xh[MM * DD];
__device__ __half g_ch[CC * DD];

// =============================== helpers ===================================
__device__ __forceinline__ uint32_t smem_u32(const void* p) {
    return (uint32_t)__cvta_generic_to_shared(p);
}
__device__ __forceinline__ void cp16(uint32_t s, const void* g) {
    asm volatile("cp.async.cg.shared.global [%0], [%1], 16;" :: "r"(s), "l"(g));
}
#define CP_COMMIT() asm volatile("cp.async.commit_group;")
#define CP_WAIT2()  asm volatile("cp.async.wait_group 2;")
#define CP_WAIT0()  asm volatile("cp.async.wait_group 0;")
#define LDM4(r0,r1,r2,r3,addr) \
    asm volatile("ldmatrix.sync.aligned.m8n8.x4.shared.b16 {%0,%1,%2,%3},[%4];" \
                 : "=r"(r0),"=r"(r1),"=r"(r2),"=r"(r3) : "r"(addr))
#define MMA16816(c,a,b) \
    asm volatile("mma.sync.aligned.m16n8k16.row.col.f32.f16.f16.f32 " \
                 "{%0,%1,%2,%3},{%4,%5,%6,%7},{%8,%9},{%0,%1,%2,%3};" \
                 : "+f"((c)[0]),"+f"((c)[1]),"+f"((c)[2]),"+f"((c)[3]) \
                 : "r"((a)[0]),"r"((a)[1]),"r"((a)[2]),"r"((a)[3]), \
                   "r"((b)[0]),"r"((b)[1]))

// sorted-4 insert (ascending, b0 = min); static indexing only
__device__ __forceinline__ void ins4(float v, int ii,
    float& b0, float& b1, float& b2, float& b3,
    int& i0, int& i1, int& i2, int& i3) {
    if (v < b3) {
        b3 = v; i3 = ii;
        if (b3 < b2) { float t = b2; b2 = b3; b3 = t; int u = i2; i2 = i3; i3 = u; }
        if (b2 < b1) { float t = b1; b1 = b2; b2 = t; int u = i1; i1 = i2; i2 = u; }
        if (b1 < b0) { float t = b0; b0 = b1; b1 = t; int u = i0; i0 = i1; i1 = u; }
    }
}

// ===========================================================================
// Kernel 1: implicit = codebook @ W^T  (fp32 SIMT, 2.1 GFLOP)
// ===========================================================================
__global__ __launch_bounds__(256) void k_implicit(const float* __restrict__ A,
                                                  const float* __restrict__ Wm) {
    __shared__ float As[8][128];
    __shared__ float Bs[8][128];
    const int tid = threadIdx.x;
    const int tx = tid & 15, ty = tid >> 4;
    const int m0 = blockIdx.x * 128;
    const int n0 = blockIdx.y * 128;
    const int lr = tid >> 1;
    const int lk = (tid & 1) * 4;

    float acc[2][2][4][4];
#pragma unroll
    for (int a = 0; a < 2; a++)
#pragma unroll
        for (int b = 0; b < 2; b++)
#pragma unroll
            for (int i = 0; i < 4; i++)
#pragma unroll
                for (int j = 0; j < 4; j++) acc[a][b][i][j] = 0.f;

    for (int k0 = 0; k0 < DD; k0 += 8) {
        float4 av = *(const float4*)&A[(size_t)(m0 + lr) * DD + k0 + lk];
        float4 bv = *(const float4*)&Wm[(size_t)(n0 + lr) * DD + k0 + lk];
        __syncthreads();
        As[lk + 0][lr] = av.x; As[lk + 1][lr] = av.y; As[lk + 2][lr] = av.z; As[lk + 3][lr] = av.w;
        Bs[lk + 0][lr] = bv.x; Bs[lk + 1][lr] = bv.y; Bs[lk + 2][lr] = bv.z; Bs[lk + 3][lr] = bv.w;
        __syncthreads();
#pragma unroll
        for (int kk = 0; kk < 8; kk++) {
            float4 a0 = *(const float4*)&As[kk][ty * 4];
            float4 a1 = *(const float4*)&As[kk][64 + ty * 4];
            float4 b0 = *(const float4*)&Bs[kk][tx * 4];
            float4 b1 = *(const float4*)&Bs[kk][64 + tx * 4];
            float ar[8] = {a0.x, a0.y, a0.z, a0.w, a1.x, a1.y, a1.z, a1.w};
            float br[8] = {b0.x, b0.y, b0.z, b0.w, b1.x, b1.y, b1.z, b1.w};
#pragma unroll
            for (int ih = 0; ih < 2; ih++)
#pragma unroll
                for (int i = 0; i < 4; i++)
#pragma unroll
                    for (int jh = 0; jh < 2; jh++)
#pragma unroll
                        for (int j = 0; j < 4; j++)
                            acc[ih][jh][i][j] += ar[ih * 4 + i] * br[jh * 4 + j];
        }
    }
#pragma unroll
    for (int ih = 0; ih < 2; ih++)
#pragma unroll
        for (int i = 0; i < 4; i++) {
            int rm = m0 + ih * 64 + ty * 4 + i;
#pragma unroll
            for (int jh = 0; jh < 2; jh++) {
                int cn = n0 + jh * 64 + tx * 4;
                float4 v = make_float4(acc[ih][jh][i][0], acc[ih][jh][i][1],
                                       acc[ih][jh][i][2], acc[ih][jh][i][3]);
                *(float4*)&g_implicit[(size_t)rm * DD + cn] = v;
            }
        }
}

// ===========================================================================
// Kernel 2: fp32 -> fp16 (screening copy)
// ===========================================================================
__global__ __launch_bounds__(256) void k_tohalf(const float* __restrict__ src,
                                                __half* __restrict__ dst, int n) {
    int i = 4 * (blockIdx.x * 256 + threadIdx.x);
    if (i >= n) return;
    float4 v = *(const float4*)(src + i);
    __half L[4] = {__float2half_rn(v.x), __float2half_rn(v.y),
                   __float2half_rn(v.z), __float2half_rn(v.w)};
    *(uint2*)(dst + i) = *(uint2*)L;
}

// ===========================================================================
// Kernel 3: halfnorm[c] = 0.5 * ||implicit[c]||^2
// ===========================================================================
__global__ __launch_bounds__(256) void k_halfnorm() {
    int warp = threadIdx.x >> 5, lane = threadIdx.x & 31;
    int row = blockIdx.x * 8 + warp;
    const float* p = g_implicit + (size_t)row * DD;
    float s = 0.f;
#pragma unroll
    for (int k = 0; k < DD / 32; k++) {
        float v = p[lane + 32 * k];
        s += v * v;
    }
#pragma unroll
    for (int o = 16; o > 0; o >>= 1) s += __shfl_xor_sync(0xffffffff, s, o);
    if (lane == 0) g_halfnorm[row] = 0.5f * s;
}

// ===========================================================================
// Kernel 4: HMMA screening GEMM (single fp16 product) + per-row top-4.
// ===========================================================================
__device__ __forceinline__ void issue_chunk(uint32_t st, int m0, int ct, int kc, int tid) {
#pragma unroll
    for (int j = 0; j < 2; j++) {
        int seg = tid * 2 + j;         // 0..511
        int r = seg >> 2, s = seg & 3;
        uint32_t so = r * (TSTR * 2) + s * 16;
        size_t go = (size_t)r * DD + kc * Bb_K + s * 8;
        cp16(st + so,              g_xh + (size_t)m0 * DD + go);
        cp16(st + TILE_BYTES + so, g_ch + (size_t)(ct * Bb_N) * DD + go);
    }
}

__global__ __launch_bounds__(256, 1) void k_screen_mma() {
    extern __shared__ char dsm[];
    __shared__ float sv[4][128][4];
    __shared__ int   si[4][128][4];

    const uint32_t sb = smem_u32(dsm);
    const int tid = threadIdx.x;
    const int lane = tid & 31;
    const int wid = tid >> 5;
    const int warp_m = wid >> 2;      // 0..1
    const int warp_n = wid & 3;       // 0..3
    const int m0 = blockIdx.x * Bb_M;
    const int gID = lane >> 2;        // 0..7
    const int tg  = lane & 3;         // 0..3

    const uint32_t aOff = (uint32_t)(warp_m * 64 + (lane & 15)) * (TSTR * 2)
                        + ((lane >> 4) << 4);
    const uint32_t bOff = (uint32_t)(warp_n * 32 + ((lane >> 4) & 1) * 8 + (lane & 7)) * (TSTR * 2)
                        + (((lane >> 3) & 1) << 4);

    // running per-row top-4 (owned by tid<128, row = m0+tid)
    float rb0 = 3.4e38f, rb1 = 3.4e38f, rb2 = 3.4e38f, rb3 = 3.4e38f;
    int   ri0 = 0, ri1 = 0, ri2 = 0, ri3 = 0;

    float acc[4][4][4];

    issue_chunk(sb + 0 * STAGE_BYTES, m0, 0, 0, tid); CP_COMMIT();
    issue_chunk(sb + 1 * STAGE_BYTES, m0, 0, 1, tid); CP_COMMIT();
    issue_chunk(sb + 2 * STAGE_BYTES, m0, 0, 2, tid); CP_COMMIT();

    for (int q = 0; q < NQ; q++) {
        const int ct = q >> 4;
        const int kc = q & 15;

        CP_WAIT2();
        __syncthreads();

        const int qn = q + 3;
        if (qn < NQ)
            issue_chunk(sb + (qn & 3) * STAGE_BYTES, m0, qn >> 4, qn & 15, tid);
        CP_COMMIT();

        if (kc == 0) {
#pragma unroll
            for (int mt = 0; mt < 4; mt++)
#pragma unroll
                for (int nt = 0; nt < 4; nt++)
#pragma unroll
                    for (int e = 0; e < 4; e++) acc[mt][nt][e] = 0.f;
        }

        const uint32_t st = sb + (q & 3) * STAGE_BYTES;
#pragma unroll
        for (int ks = 0; ks < 2; ks++) {
            uint32_t aF[4][4], bF[4][2];
#pragma unroll
            for (int mt = 0; mt < 4; mt++)
                LDM4(aF[mt][0], aF[mt][1], aF[mt][2], aF[mt][3],
                     st + aOff + mt * (16 * TSTR * 2) + ks * 32);
#pragma unroll
            for (int p = 0; p < 2; p++) {
                uint32_t r0, r1, r2, r3;
                LDM4(r0, r1, r2, r3,
                     st + TILE_BYTES + bOff + p * (16 * TSTR * 2) + ks * 32);
                bF[2 * p][0] = r0; bF[2 * p][1] = r1;
                bF[2 * p + 1][0] = r2; bF[2 * p + 1][1] = r3;
            }
#pragma unroll
            for (int mt = 0; mt < 4; mt++)
#pragma unroll
                for (int nt = 0; nt < 4; nt++) MMA16816(acc[mt][nt], aF[mt], bF[nt]);
        }

        if (kc == 15) {
            // -------- top-4 epilogue for this c-tile --------
#pragma unroll
            for (int mt = 0; mt < 4; mt++) {
#pragma unroll
                for (int half = 0; half < 2; half++) {
                    float b0 = 3.4e38f, b1 = 3.4e38f, b2 = 3.4e38f, b3 = 3.4e38f;
                    int   i0 = 0, i1 = 0, i2 = 0, i3 = 0;
#pragma unroll
                    for (int nt = 0; nt < 4; nt++) {
#pragma unroll
                        for (int j = 0; j < 2; j++) {
                            int c = ct * Bb_N + warp_n * 32 + nt * 8 + tg * 2 + j;
                            float s = __ldg(&g_halfnorm[c]) - acc[mt][nt][2 * half + j];
                            ins4(s, c, b0, b1, b2, b3, i0, i1, i2, i3);
                        }
                    }
                    // merge top-4 across the 4 tg lanes (xor 1, then xor 2)
#pragma unroll
                    for (int off = 1; off <= 2; off <<= 1) {
                        float ob0 = __shfl_xor_sync(0xffffffff, b0, off);
                        float ob1 = __shfl_xor_sync(0xffffffff, b1, off);
                        float ob2 = __shfl_xor_sync(0xffffffff, b2, off);
                        float ob3 = __shfl_xor_sync(0xffffffff, b3, off);
                        int oi0 = __shfl_xor_sync(0xffffffff, i0, off);
                        int oi1 = __shfl_xor_sync(0xffffffff, i1, off);
                        int oi2 = __shfl_xor_sync(0xffffffff, i2, off);
                        int oi3 = __shfl_xor_sync(0xffffffff, i3, off);
                        ins4(ob0, oi0, b0, b1, b2, b3, i0, i1, i2, i3);
                        ins4(ob1, oi1, b0, b1, b2, b3, i0, i1, i2, i3);
                        ins4(ob2, oi2, b0, b1, b2, b3, i0, i1, i2, i3);
                        ins4(ob3, oi3, b0, b1, b2, b3, i0, i1, i2, i3);
                    }
                    if (tg == 0) {
                        int r = warp_m * 64 + mt * 16 + gID + 8 * half;
                        sv[warp_n][r][0] = b0; sv[warp_n][r][1] = b1;
                        sv[warp_n][r][2] = b2; sv[warp_n][r][3] = b3;
                        si[warp_n][r][0] = i0; si[warp_n][r][1] = i1;
                        si[warp_n][r][2] = i2; si[warp_n][r][3] = i3;
                    }
                }
            }
            __syncthreads();
            if (tid < 128) {
#pragma unroll
                for (int wn = 0; wn < 4; wn++)
#pragma unroll
                    for (int s = 0; s < 4; s++)
                        ins4(sv[wn][tid][s], si[wn][tid][s],
                             rb0, rb1, rb2, rb3, ri0, ri1, ri2, ri3);
            }
            __syncthreads();
        }
    }

    if (tid < 128) {
        int gm = m0 + tid;
        g_cand[gm * 4 + 0] = ri0;
        g_cand[gm * 4 + 1] = ri1;
        g_cand[gm * 4 + 2] = ri2;
        g_cand[gm * 4 + 3] = ri3;
    }
}

// ===========================================================================
// Kernel 5: exact fp32 rescore of the 4 candidates. One warp per row.
// ===========================================================================
__global__ __launch_bounds__(256) void k_rescore(const float* __restrict__ X,
                                                 float* __restrict__ out_idx_f) {
    const int warp = threadIdx.x >> 5, lane = threadIdx.x & 31;
    const int m = blockIdx.x * 8 + warp;
    const float* xr = X + (size_t)m * DD;

    float4 xv[4];
#pragma unroll
    for (int t = 0; t < 4; t++) xv[t] = ((const float4*)xr)[lane + 32 * t];

    float bestv = 3.4e38f;
    int   besti = 0x7fffffff;
#pragma unroll
    for (int k = 0; k < 4; k++) {
        int ci = g_cand[m * 4 + k];
        const float4* cr = (const float4*)(g_implicit + (size_t)ci * DD);
        float dot = 0.f;
#pragma unroll
        for (int t = 0; t < 4; t++) {
            float4 cv = cr[lane + 32 * t];
            dot += xv[t].x * cv.x + xv[t].y * cv.y + xv[t].z * cv.z + xv[t].w * cv.w;
        }
#pragma unroll
        for (int o = 16; o > 0; o >>= 1) dot += __shfl_xor_sync(0xffffffff, dot, o);
        float s = g_halfnorm[ci] - dot;
        if (s < bestv || (s == bestv && ci < besti)) { bestv = s; besti = ci; }
    }
    if (lane == 0) {
        g_idx[m] = besti;
        out_idx_f[m] = (float)besti;
    }
}

// ===========================================================================
// Kernel 6: rotation trick + per-row commit sum. One block per x-row.
// ===========================================================================
__global__ __launch_bounds__(128) void k_rot(const float* __restrict__ X,
                                             float* __restrict__ outq) {
    __shared__ float red[4][4];
    const int m = blockIdx.x;
    const int t = threadIdx.x;
    const float* xr = X + (size_t)m * DD;
    const float* qr = g_implicit + (size_t)g_idx[m] * DD;

    float4 xv = ((const float4*)xr)[t];
    float4 qv = ((const float4*)qr)[t];

    float sx  = xv.x * xv.x + xv.y * xv.y + xv.z * xv.z + xv.w * xv.w;
    float sq  = qv.x * qv.x + qv.y * qv.y + qv.z * qv.z + qv.w * qv.w;
    float sxq = xv.x * qv.x + xv.y * qv.y + xv.z * qv.z + xv.w * qv.w;
    float d0 = xv.x - qv.x + 1e-6f, d1 = xv.y - qv.y + 1e-6f;
    float d2 = xv.z - qv.z + 1e-6f, d3 = xv.w - qv.w + 1e-6f;
    float sc = d0 * d0 + d1 * d1 + d2 * d2 + d3 * d3;

#pragma unroll
    for (int o = 16; o > 0; o >>= 1) {
        sx  += __shfl_xor_sync(0xffffffff, sx, o);
        sq  += __shfl_xor_sync(0xffffffff, sq, o);
        sxq += __shfl_xor_sync(0xffffffff, sxq, o);
        sc  += __shfl_xor_sync(0xffffffff, sc, o);
    }
    int warp = t >> 5, lane = t & 31;
    if (lane == 0) { red[warp][0] = sx; red[warp][1] = sq; red[warp][2] = sxq; red[warp][3] = sc; }
    __syncthreads();
    sx  = red[0][0] + red[1][0] + red[2][0] + red[3][0];
    sq  = red[0][1] + red[1][1] + red[2][1] + red[3][1];
    sxq = red[0][2] + red[1][2] + red[2][2] + red[3][2];
    sc  = red[0][3] + red[1][3] + red[2][3] + red[3][3];

    if (t == 0) g_commit[m] = sc;

    float norm_x = sqrtf(sx), norm_q = sqrtf(sq);
    float nx = fmaxf(norm_x, 1e-6f);
    float nq = fmaxf(norm_q, 1e-6f);
    float uq2 = sx / (nx * nx) + sq / (nq * nq) + 2.f * sxq / (nx * nq);
    float nuq = sqrtf(fmaxf(uq2, 0.f));
    float wden = fmaxf(nuq, 1e-12f);
    float e_w = (sx / nx + sxq / nq) / wden;
    float e_u = sx / nx;
    float c1 = 2.f * e_w / wden;
    float c2 = 2.f * e_u;
    float scale = norm_q / nx;
    float coef_x = (1.f - c1 / nx) * scale;
    float coef_q = ((c2 - c1) / nq) * scale;

    float4 ov;
    ov.x = coef_x * xv.x + coef_q * qv.x;
    ov.y = coef_x * xv.y + coef_q * qv.y;
    ov.z = coef_x * xv.z + coef_q * qv.z;
    ov.w = coef_x * xv.w + coef_q * qv.w;
    ((float4*)(outq + (size_t)m * DD))[t] = ov;
}

// ===========================================================================
// Kernel 7: deterministic loss reduction
// ===========================================================================
__global__ __launch_bounds__(256) void k_loss(float* __restrict__ out_loss) {
    __shared__ float s[256];
    float v = 0.f;
    for (int i = threadIdx.x; i < MM; i += 256) v += g_commit[i];
    s[threadIdx.x] = v;
    __syncthreads();
    for (int o = 128; o > 0; o >>= 1) {
        if (threadIdx.x < o) s[threadIdx.x] += s[threadIdx.x + o];
        __syncthreads();
    }
    if (threadIdx.x == 0) out_loss[0] = s[0] / (float)MM;
}

// ===========================================================================
extern "C" void kernel_launch(void* const* d_in, const int* in_sizes, int n_in,
                              void* d_out, int out_size) {
    const float* x  = (const float*)d_in[0];
    const float* cb = (const float*)d_in[1];
    const float* Wm = (const float*)d_in[2];
    float* out = (float*)d_out;

    int idx_off  = out_size - MM - 1;
    int loss_off = out_size - 1;

    static bool attr_done = false;
    if (!attr_done) {
        cudaFuncSetAttribute(k_screen_mma, cudaFuncAttributeMaxDynamicSharedMemorySize, SMEM_DYN);
        attr_done = true;
    }

    __half *xh, *ch; float* imp;
    cudaGetSymbolAddress((void**)&xh, g_xh);
    cudaGetSymbolAddress((void**)&ch, g_ch);
    cudaGetSymbolAddress((void**)&imp, g_implicit);

    k_implicit<<<dim3(CC / 128, DD / 128), 256>>>(cb, Wm);
    k_tohalf<<<(MM * DD / 4 + 255) / 256, 256>>>(x, xh, MM * DD);
    k_tohalf<<<(CC * DD / 4 + 255) / 256, 256>>>(imp, ch, CC * DD);
    k_halfnorm<<<CC / 8, 256>>>();
    k_screen_mma<<<MM / Bb_M, 256, SMEM_DYN>>>();
    k_rescore<<<MM / 8, 256>>>(x, out + idx_off);
    k_rot<<<MM, 128>>>(x, out);
    k_loss<<<1, 256>>>(out + loss_off);
}

// round 7
// speedup vs baseline: 4.0018x; 1.2682x over previous
#include <cuda_runtime.h>
#include <cuda_fp16.h>
#include <cstdint>

#define BB 8
#define NN 2048
#define DD 512
#define CC 4096
#define MM (BB*NN)   // 16384

// screen-kernel tiling
#define Bb_M 128
#define Bb_N 128
#define Bb_K 64                   // k-depth per B chunk
#define NCT (CC/Bb_N)             // 32 c-tiles
#define NKC (DD/Bb_K)             // 8 k-chunks per c-tile
#define NQ  (NCT*NKC)             // 256 chunks
#define KB_BYTES 16384            // 128 rows x 64 halfs (128B) per block
#define A_BYTES  (8*KB_BYTES)     // resident A: 128 x 512 fp16 = 128KB
#define BSTAGES 4
#define SMEM_DYN (A_BYTES + BSTAGES*KB_BYTES)   // 192KB

// ---------------- scratch ----------------
__device__ float g_implicit[CC * DD];
__device__ float g_halfnorm[CC];
__device__ int   g_idx[MM];
__device__ int   g_cand[MM * 4];
__device__ float g_commit[MM];
__device__ __half g_xh[MM * DD];
__device__ __half g_ch[CC * DD];

// =============================== helpers ===================================
__device__ __forceinline__ uint32_t smem_u32(const void* p) {
    return (uint32_t)__cvta_generic_to_shared(p);
}
__device__ __forceinline__ void cp16(uint32_t s, const void* g) {
    asm volatile("cp.async.cg.shared.global [%0], [%1], 16;" :: "r"(s), "l"(g));
}
#define CP_COMMIT() asm volatile("cp.async.commit_group;")
#define CP_WAIT2()  asm volatile("cp.async.wait_group 2;")
#define LDM4(r0,r1,r2,r3,addr) \
    asm volatile("ldmatrix.sync.aligned.m8n8.x4.shared.b16 {%0,%1,%2,%3},[%4];" \
                 : "=r"(r0),"=r"(r1),"=r"(r2),"=r"(r3) : "r"(addr))
#define MMA16816(c,a,b) \
    asm volatile("mma.sync.aligned.m16n8k16.row.col.f32.f16.f16.f32 " \
                 "{%0,%1,%2,%3},{%4,%5,%6,%7},{%8,%9},{%0,%1,%2,%3};" \
                 : "+f"((c)[0]),"+f"((c)[1]),"+f"((c)[2]),"+f"((c)[3]) \
                 : "r"((a)[0]),"r"((a)[1]),"r"((a)[2]),"r"((a)[3]), \
                   "r"((b)[0]),"r"((b)[1]))

// sorted-4 insert (ascending, b0 = min); static indexing only
__device__ __forceinline__ void ins4(float v, int ii,
    float& b0, float& b1, float& b2, float& b3,
    int& i0, int& i1, int& i2, int& i3) {
    if (v < b3) {
        b3 = v; i3 = ii;
        if (b3 < b2) { float t = b2; b2 = b3; b3 = t; int u = i2; i2 = i3; i3 = u; }
        if (b2 < b1) { float t = b1; b1 = b2; b2 = t; int u = i1; i1 = i2; i2 = u; }
        if (b1 < b0) { float t = b0; b0 = b1; b1 = t; int u = i0; i0 = i1; i1 = u; }
    }
}

// ===========================================================================
// Kernel 1: implicit = codebook @ W^T  (fp32 SIMT, 2.1 GFLOP)
// ===========================================================================
__global__ __launch_bounds__(256) void k_implicit(const float* __restrict__ A,
                                                  const float* __restrict__ Wm) {
    __shared__ float As[8][128];
    __shared__ float Bs[8][128];
    const int tid = threadIdx.x;
    const int tx = tid & 15, ty = tid >> 4;
    const int m0 = blockIdx.x * 128;
    const int n0 = blockIdx.y * 128;
    const int lr = tid >> 1;
    const int lk = (tid & 1) * 4;

    float acc[2][2][4][4];
#pragma unroll
    for (int a = 0; a < 2; a++)
#pragma unroll
        for (int b = 0; b < 2; b++)
#pragma unroll
            for (int i = 0; i < 4; i++)
#pragma unroll
                for (int j = 0; j < 4; j++) acc[a][b][i][j] = 0.f;

    for (int k0 = 0; k0 < DD; k0 += 8) {
        float4 av = *(const float4*)&A[(size_t)(m0 + lr) * DD + k0 + lk];
        float4 bv = *(const float4*)&Wm[(size_t)(n0 + lr) * DD + k0 + lk];
        __syncthreads();
        As[lk + 0][lr] = av.x; As[lk + 1][lr] = av.y; As[lk + 2][lr] = av.z; As[lk + 3][lr] = av.w;
        Bs[lk + 0][lr] = bv.x; Bs[lk + 1][lr] = bv.y; Bs[lk + 2][lr] = bv.z; Bs[lk + 3][lr] = bv.w;
        __syncthreads();
#pragma unroll
        for (int kk = 0; kk < 8; kk++) {
            float4 a0 = *(const float4*)&As[kk][ty * 4];
            float4 a1 = *(const float4*)&As[kk][64 + ty * 4];
            float4 b0 = *(const float4*)&Bs[kk][tx * 4];
            float4 b1 = *(const float4*)&Bs[kk][64 + tx * 4];
            float ar[8] = {a0.x, a0.y, a0.z, a0.w, a1.x, a1.y, a1.z, a1.w};
            float br[8] = {b0.x, b0.y, b0.z, b0.w, b1.x, b1.y, b1.z, b1.w};
#pragma unroll
            for (int ih = 0; ih < 2; ih++)
#pragma unroll
                for (int i = 0; i < 4; i++)
#pragma unroll
                    for (int jh = 0; jh < 2; jh++)
#pragma unroll
                        for (int j = 0; j < 4; j++)
                            acc[ih][jh][i][j] += ar[ih * 4 + i] * br[jh * 4 + j];
        }
    }
#pragma unroll
    for (int ih = 0; ih < 2; ih++)
#pragma unroll
        for (int i = 0; i < 4; i++) {
            int rm = m0 + ih * 64 + ty * 4 + i;
#pragma unroll
            for (int jh = 0; jh < 2; jh++) {
                int cn = n0 + jh * 64 + tx * 4;
                float4 v = make_float4(acc[ih][jh][i][0], acc[ih][jh][i][1],
                                       acc[ih][jh][i][2], acc[ih][jh][i][3]);
                *(float4*)&g_implicit[(size_t)rm * DD + cn] = v;
            }
        }
}

// ===========================================================================
// Kernel 2: fp32 -> fp16 (screening copy)
// ===========================================================================
__global__ __launch_bounds__(256) void k_tohalf(const float* __restrict__ src,
                                                __half* __restrict__ dst, int n) {
    int i = 4 * (blockIdx.x * 256 + threadIdx.x);
    if (i >= n) return;
    float4 v = *(const float4*)(src + i);
    __half L[4] = {__float2half_rn(v.x), __float2half_rn(v.y),
                   __float2half_rn(v.z), __float2half_rn(v.w)};
    *(uint2*)(dst + i) = *(uint2*)L;
}

// ===========================================================================
// Kernel 3: halfnorm[c] = 0.5 * ||implicit[c]||^2
// ===========================================================================
__global__ __launch_bounds__(256) void k_halfnorm() {
    int warp = threadIdx.x >> 5, lane = threadIdx.x & 31;
    int row = blockIdx.x * 8 + warp;
    const float* p = g_implicit + (size_t)row * DD;
    float s = 0.f;
#pragma unroll
    for (int k = 0; k < DD / 32; k++) {
        float v = p[lane + 32 * k];
        s += v * v;
    }
#pragma unroll
    for (int o = 16; o > 0; o >>= 1) s += __shfl_xor_sync(0xffffffff, s, o);
    if (lane == 0) g_halfnorm[row] = 0.5f * s;
}

// ===========================================================================
// Kernel 4: HMMA screening GEMM + per-row top-4.
// A tile resident in smem (swizzled); B streamed in k=64 chunks, 4 stages.
// swizzle: phys = row*128 + ((seg ^ (row&7))<<4), seg = 16B column segment.
// ===========================================================================
__device__ __forceinline__ void issue_b(uint32_t st, int ct, int kc, int tid) {
#pragma unroll
    for (int j = 0; j < 4; j++) {
        int idx = j * 256 + tid;          // 0..1023
        int row = idx >> 3, seg = idx & 7;
        const __half* g = g_ch + (size_t)(ct * Bb_N + row) * DD + kc * Bb_K + seg * 8;
        cp16(st + row * 128 + (((seg ^ (row & 7))) << 4), g);
    }
}

__global__ __launch_bounds__(256, 1) void k_screen_mma() {
    extern __shared__ char dsm[];
    __shared__ float sv[4][128][4];
    __shared__ int   si[4][128][4];

    const uint32_t sa = smem_u32(dsm);            // A resident, 128KB
    const uint32_t sbB = sa + A_BYTES;            // B stages
    const int tid = threadIdx.x;
    const int lane = tid & 31;
    const int wid = tid >> 5;
    const int warp_m = wid >> 2;      // 0..1
    const int warp_n = wid & 3;       // 0..3
    const int m0 = blockIdx.x * Bb_M;
    const int gID = lane >> 2;        // 0..7
    const int tg  = lane & 3;         // 0..3

    // A-row base (row = warp_m*64 + mt*16 + (lane&15); row&7 == lane&7)
    const uint32_t aRow = (uint32_t)(warp_m * 64 + (lane & 15)) * 128;
    const uint32_t bRow = (uint32_t)(warp_n * 32 + ((lane >> 4) & 1) * 8 + (lane & 7)) * 128;
    const int lxor = lane & 7;

    // running per-row top-4 (owned by tid<128, row = m0+tid)
    float rb0 = 3.4e38f, rb1 = 3.4e38f, rb2 = 3.4e38f, rb3 = 3.4e38f;
    int   ri0 = 0, ri1 = 0, ri2 = 0, ri3 = 0;

    float acc[4][4][4];

    // ---- prologue: resident A (8192 segs) + B stage 0, then B1, B2 ----
#pragma unroll
    for (int t = 0; t < 32; t++) {
        int idx = t * 256 + tid;          // 0..8191
        int row = idx >> 6, s = idx & 63;
        int kb = s >> 3, seg = s & 7;
        const __half* g = g_xh + (size_t)(m0 + row) * DD + kb * 64 + seg * 8;
        cp16(sa + kb * KB_BYTES + row * 128 + ((seg ^ (row & 7)) << 4), g);
    }
    issue_b(sbB + 0 * KB_BYTES, 0, 0, tid); CP_COMMIT();
    issue_b(sbB + 1 * KB_BYTES, 0, 1, tid); CP_COMMIT();
    issue_b(sbB + 2 * KB_BYTES, 0, 2, tid); CP_COMMIT();

    for (int q = 0; q < NQ; q++) {
        const int ct = q >> 3;
        const int kc = q & 7;

        CP_WAIT2();          // chunk q (and A, at q=0) resident
        __syncthreads();

        const int qn = q + 3;
        if (qn < NQ)
            issue_b(sbB + (qn & 3) * KB_BYTES, qn >> 3, qn & 7, tid);
        CP_COMMIT();

        if (kc == 0) {
#pragma unroll
            for (int mt = 0; mt < 4; mt++)
#pragma unroll
                for (int nt = 0; nt < 4; nt++)
#pragma unroll
                    for (int e = 0; e < 4; e++) acc[mt][nt][e] = 0.f;
        }

        const uint32_t aBase = sa + kc * KB_BYTES;
        const uint32_t bBase = sbB + (q & 3) * KB_BYTES;
#pragma unroll
        for (int ks = 0; ks < 4; ks++) {
            const uint32_t aSw = (uint32_t)(((ks * 2 + (lane >> 4)) ^ lxor) << 4);
            const uint32_t bSw = (uint32_t)(((ks * 2 + ((lane >> 3) & 1)) ^ lxor) << 4);
            uint32_t aF[4][4], bF[4][2];
#pragma unroll
            for (int mt = 0; mt < 4; mt++)
                LDM4(aF[mt][0], aF[mt][1], aF[mt][2], aF[mt][3],
                     aBase + aRow + mt * (16 * 128) + aSw);
#pragma unroll
            for (int p = 0; p < 2; p++) {
                uint32_t r0, r1, r2, r3;
                LDM4(r0, r1, r2, r3, bBase + bRow + p * (16 * 128) + bSw);
                bF[2 * p][0] = r0; bF[2 * p][1] = r1;
                bF[2 * p + 1][0] = r2; bF[2 * p + 1][1] = r3;
            }
#pragma unroll
            for (int mt = 0; mt < 4; mt++)
#pragma unroll
                for (int nt = 0; nt < 4; nt++) MMA16816(acc[mt][nt], aF[mt], bF[nt]);
        }

        if (kc == 7) {
            // -------- top-4 epilogue for this c-tile --------
#pragma unroll
            for (int mt = 0; mt < 4; mt++) {
#pragma unroll
                for (int half = 0; half < 2; half++) {
                    float b0 = 3.4e38f, b1 = 3.4e38f, b2 = 3.4e38f, b3 = 3.4e38f;
                    int   i0 = 0, i1 = 0, i2 = 0, i3 = 0;
#pragma unroll
                    for (int nt = 0; nt < 4; nt++) {
#pragma unroll
                        for (int j = 0; j < 2; j++) {
                            int c = ct * Bb_N + warp_n * 32 + nt * 8 + tg * 2 + j;
                            float s = __ldg(&g_halfnorm[c]) - acc[mt][nt][2 * half + j];
                            ins4(s, c, b0, b1, b2, b3, i0, i1, i2, i3);
                        }
                    }
#pragma unroll
                    for (int off = 1; off <= 2; off <<= 1) {
                        float ob0 = __shfl_xor_sync(0xffffffff, b0, off);
                        float ob1 = __shfl_xor_sync(0xffffffff, b1, off);
                        float ob2 = __shfl_xor_sync(0xffffffff, b2, off);
                        float ob3 = __shfl_xor_sync(0xffffffff, b3, off);
                        int oi0 = __shfl_xor_sync(0xffffffff, i0, off);
                        int oi1 = __shfl_xor_sync(0xffffffff, i1, off);
                        int oi2 = __shfl_xor_sync(0xffffffff, i2, off);
                        int oi3 = __shfl_xor_sync(0xffffffff, i3, off);
                        ins4(ob0, oi0, b0, b1, b2, b3, i0, i1, i2, i3);
                        ins4(ob1, oi1, b0, b1, b2, b3, i0, i1, i2, i3);
                        ins4(ob2, oi2, b0, b1, b2, b3, i0, i1, i2, i3);
                        ins4(ob3, oi3, b0, b1, b2, b3, i0, i1, i2, i3);
                    }
                    if (tg == 0) {
                        int r = warp_m * 64 + mt * 16 + gID + 8 * half;
                        sv[warp_n][r][0] = b0; sv[warp_n][r][1] = b1;
                        sv[warp_n][r][2] = b2; sv[warp_n][r][3] = b3;
                        si[warp_n][r][0] = i0; si[warp_n][r][1] = i1;
                        si[warp_n][r][2] = i2; si[warp_n][r][3] = i3;
                    }
                }
            }
            __syncthreads();
            if (tid < 128) {
#pragma unroll
                for (int wn = 0; wn < 4; wn++)
#pragma unroll
                    for (int s = 0; s < 4; s++)
                        ins4(sv[wn][tid][s], si[wn][tid][s],
                             rb0, rb1, rb2, rb3, ri0, ri1, ri2, ri3);
            }
            __syncthreads();
        }
    }

    if (tid < 128) {
        int gm = m0 + tid;
        g_cand[gm * 4 + 0] = ri0;
        g_cand[gm * 4 + 1] = ri1;
        g_cand[gm * 4 + 2] = ri2;
        g_cand[gm * 4 + 3] = ri3;
    }
}

// ===========================================================================
// Kernel 5: exact fp32 rescore of the 4 candidates. One warp per row.
// ===========================================================================
__global__ __launch_bounds__(256) void k_rescore(const float* __restrict__ X,
                                                 float* __restrict__ out_idx_f) {
    const int warp = threadIdx.x >> 5, lane = threadIdx.x & 31;
    const int m = blockIdx.x * 8 + warp;
    const float* xr = X + (size_t)m * DD;

    float4 xv[4];
#pragma unroll
    for (int t = 0; t < 4; t++) xv[t] = ((const float4*)xr)[lane + 32 * t];

    float bestv = 3.4e38f;
    int   besti = 0x7fffffff;
#pragma unroll
    for (int k = 0; k < 4; k++) {
        int ci = g_cand[m * 4 + k];
        const float4* cr = (const float4*)(g_implicit + (size_t)ci * DD);
        float dot = 0.f;
#pragma unroll
        for (int t = 0; t < 4; t++) {
            float4 cv = cr[lane + 32 * t];
            dot += xv[t].x * cv.x + xv[t].y * cv.y + xv[t].z * cv.z + xv[t].w * cv.w;
        }
#pragma unroll
        for (int o = 16; o > 0; o >>= 1) dot += __shfl_xor_sync(0xffffffff, dot, o);
        float s = g_halfnorm[ci] - dot;
        if (s < bestv || (s == bestv && ci < besti)) { bestv = s; besti = ci; }
    }
    if (lane == 0) {
        g_idx[m] = besti;
        out_idx_f[m] = (float)besti;
    }
}

// ===========================================================================
// Kernel 6: rotation trick + per-row commit sum. One block per x-row.
// ===========================================================================
__global__ __launch_bounds__(128) void k_rot(const float* __restrict__ X,
                                             float* __restrict__ outq) {
    __shared__ float red[4][4];
    const int m = blockIdx.x;
    const int t = threadIdx.x;
    const float* xr = X + (size_t)m * DD;
    const float* qr = g_implicit + (size_t)g_idx[m] * DD;

    float4 xv = ((const float4*)xr)[t];
    float4 qv = ((const float4*)qr)[t];

    float sx  = xv.x * xv.x + xv.y * xv.y + xv.z * xv.z + xv.w * xv.w;
    float sq  = qv.x * qv.x + qv.y * qv.y + qv.z * qv.z + qv.w * qv.w;
    float sxq = xv.x * qv.x + xv.y * qv.y + xv.z * qv.z + xv.w * qv.w;
    float d0 = xv.x - qv.x + 1e-6f, d1 = xv.y - qv.y + 1e-6f;
    float d2 = xv.z - qv.z + 1e-6f, d3 = xv.w - qv.w + 1e-6f;
    float sc = d0 * d0 + d1 * d1 + d2 * d2 + d3 * d3;

#pragma unroll
    for (int o = 16; o > 0; o >>= 1) {
        sx  += __shfl_xor_sync(0xffffffff, sx, o);
        sq  += __shfl_xor_sync(0xffffffff, sq, o);
        sxq += __shfl_xor_sync(0xffffffff, sxq, o);
        sc  += __shfl_xor_sync(0xffffffff, sc, o);
    }
    int warp = t >> 5, lane = t & 31;
    if (lane == 0) { red[warp][0] = sx; red[warp][1] = sq; red[warp][2] = sxq; red[warp][3] = sc; }
    __syncthreads();
    sx  = red[0][0] + red[1][0] + red[2][0] + red[3][0];
    sq  = red[0][1] + red[1][1] + red[2][1] + red[3][1];
    sxq = red[0][2] + red[1][2] + red[2][2] + red[3][2];
    sc  = red[0][3] + red[1][3] + red[2][3] + red[3][3];

    if (t == 0) g_commit[m] = sc;

    float norm_x = sqrtf(sx), norm_q = sqrtf(sq);
    float nx = fmaxf(norm_x, 1e-6f);
    float nq = fmaxf(norm_q, 1e-6f);
    float uq2 = sx / (nx * nx) + sq / (nq * nq) + 2.f * sxq / (nx * nq);
    float nuq = sqrtf(fmaxf(uq2, 0.f));
    float wden = fmaxf(nuq, 1e-12f);
    float e_w = (sx / nx + sxq / nq) / wden;
    float e_u = sx / nx;
    float c1 = 2.f * e_w / wden;
    float c2 = 2.f * e_u;
    float scale = norm_q / nx;
    float coef_x = (1.f - c1 / nx) * scale;
    float coef_q = ((c2 - c1) / nq) * scale;

    float4 ov;
    ov.x = coef_x * xv.x + coef_q * qv.x;
    ov.y = coef_x * xv.y + coef_q * qv.y;
    ov.z = coef_x * xv.z + coef_q * qv.z;
    ov.w = coef_x * xv.w + coef_q * qv.w;
    ((float4*)(outq + (size_t)m * DD))[t] = ov;
}

// ===========================================================================
// Kernel 7: deterministic loss reduction
// ===========================================================================
__global__ __launch_bounds__(256) void k_loss(float* __restrict__ out_loss) {
    __shared__ float s[256];
    float v = 0.f;
    for (int i = threadIdx.x; i < MM; i += 256) v += g_commit[i];
    s[threadIdx.x] = v;
    __syncthreads();
    for (int o = 128; o > 0; o >>= 1) {
        if (threadIdx.x < o) s[threadIdx.x] += s[threadIdx.x + o];
        __syncthreads();
    }
    if (threadIdx.x == 0) out_loss[0] = s[0] / (float)MM;
}

// ===========================================================================
extern "C" void kernel_launch(void* const* d_in, const int* in_sizes, int n_in,
                              void* d_out, int out_size) {
    const float* x  = (const float*)d_in[0];
    const float* cb = (const float*)d_in[1];
    const float* Wm = (const float*)d_in[2];
    float* out = (float*)d_out;

    int idx_off  = out_size - MM - 1;
    int loss_off = out_size - 1;

    static bool attr_done = false;
    if (!attr_done) {
        cudaFuncSetAttribute(k_screen_mma, cudaFuncAttributeMaxDynamicSharedMemorySize, SMEM_DYN);
        attr_done = true;
    }

    __half *xh, *ch; float* imp;
    cudaGetSymbolAddress((void**)&xh, g_xh);
    cudaGetSymbolAddress((void**)&ch, g_ch);
    cudaGetSymbolAddress((void**)&imp, g_implicit);

    k_implicit<<<dim3(CC / 128, DD / 128), 256>>>(cb, Wm);
    k_tohalf<<<(MM * DD / 4 + 255) / 256, 256>>>(x, xh, MM * DD);
    k_tohalf<<<(CC * DD / 4 + 255) / 256, 256>>>(imp, ch, CC * DD);
    k_halfnorm<<<CC / 8, 256>>>();
    k_screen_mma<<<MM / Bb_M, 256, SMEM_DYN>>>();
    k_rescore<<<MM / 8, 256>>>(x, out + idx_off);
    k_rot<<<MM, 128>>>(x, out);
    k_loss<<<1, 256>>>(out + loss_off);
}

// round 8
// speedup vs baseline: 4.5580x; 1.1390x over previous
#include <cuda_runtime.h>
#include <cuda_fp16.h>
#include <cstdint>

#define BB 8
#define NN 2048
#define DD 512
#define CC 4096
#define MM (BB*NN)   // 16384

// screen-kernel tiling
#define Bb_M 128
#define Bb_N 128
#define Bb_K 64                   // k-depth per B chunk
#define NCT (CC/Bb_N)             // 32 c-tiles
#define NKC (DD/Bb_K)             // 8 k-chunks per c-tile
#define NQ  (NCT*NKC)             // 256 chunks
#define KB_BYTES 16384            // 128 rows x 64 halfs (128B) per block
#define A_BYTES  (8*KB_BYTES)     // resident A: 128 x 512 fp16 = 128KB
#define BSTAGES 4
#define SMEM_DYN (A_BYTES + BSTAGES*KB_BYTES)   // 192KB
#define NTHR 512

// ---------------- scratch ----------------
__device__ float g_implicit[CC * DD];
__device__ float g_halfnorm[CC];
__device__ int   g_idx[MM];
__device__ int   g_cand[MM * 4];
__device__ float g_commit[MM];
__device__ __half g_xh[MM * DD];
__device__ __half g_ch[CC * DD];

// =============================== helpers ===================================
__device__ __forceinline__ uint32_t smem_u32(const void* p) {
    return (uint32_t)__cvta_generic_to_shared(p);
}
__device__ __forceinline__ void cp16(uint32_t s, const void* g) {
    asm volatile("cp.async.cg.shared.global [%0], [%1], 16;" :: "r"(s), "l"(g));
}
#define CP_COMMIT() asm volatile("cp.async.commit_group;")
#define CP_WAIT2()  asm volatile("cp.async.wait_group 2;")
#define LDM4(r0,r1,r2,r3,addr) \
    asm volatile("ldmatrix.sync.aligned.m8n8.x4.shared.b16 {%0,%1,%2,%3},[%4];" \
                 : "=r"(r0),"=r"(r1),"=r"(r2),"=r"(r3) : "r"(addr))
#define MMA16816(c,a,b) \
    asm volatile("mma.sync.aligned.m16n8k16.row.col.f32.f16.f16.f32 " \
                 "{%0,%1,%2,%3},{%4,%5,%6,%7},{%8,%9},{%0,%1,%2,%3};" \
                 : "+f"((c)[0]),"+f"((c)[1]),"+f"((c)[2]),"+f"((c)[3]) \
                 : "r"((a)[0]),"r"((a)[1]),"r"((a)[2]),"r"((a)[3]), \
                   "r"((b)[0]),"r"((b)[1]))

// sorted-4 insert (ascending, b0 = min); static indexing only
__device__ __forceinline__ void ins4(float v, int ii,
    float& b0, float& b1, float& b2, float& b3,
    int& i0, int& i1, int& i2, int& i3) {
    if (v < b3) {
        b3 = v; i3 = ii;
        if (b3 < b2) { float t = b2; b2 = b3; b3 = t; int u = i2; i2 = i3; i3 = u; }
        if (b2 < b1) { float t = b1; b1 = b2; b2 = t; int u = i1; i1 = i2; i2 = u; }
        if (b1 < b0) { float t = b0; b0 = b1; b1 = t; int u = i0; i0 = i1; i1 = u; }
    }
}

// ===========================================================================
// Kernel 1: implicit = codebook @ W^T  (fp32 SIMT, 2.1 GFLOP)
// ===========================================================================
__global__ __launch_bounds__(256) void k_implicit(const float* __restrict__ A,
                                                  const float* __restrict__ Wm) {
    __shared__ float As[8][128];
    __shared__ float Bs[8][128];
    const int tid = threadIdx.x;
    const int tx = tid & 15, ty = tid >> 4;
    const int m0 = blockIdx.x * 128;
    const int n0 = blockIdx.y * 128;
    const int lr = tid >> 1;
    const int lk = (tid & 1) * 4;

    float acc[2][2][4][4];
#pragma unroll
    for (int a = 0; a < 2; a++)
#pragma unroll
        for (int b = 0; b < 2; b++)
#pragma unroll
            for (int i = 0; i < 4; i++)
#pragma unroll
                for (int j = 0; j < 4; j++) acc[a][b][i][j] = 0.f;

    for (int k0 = 0; k0 < DD; k0 += 8) {
        float4 av = *(const float4*)&A[(size_t)(m0 + lr) * DD + k0 + lk];
        float4 bv = *(const float4*)&Wm[(size_t)(n0 + lr) * DD + k0 + lk];
        __syncthreads();
        As[lk + 0][lr] = av.x; As[lk + 1][lr] = av.y; As[lk + 2][lr] = av.z; As[lk + 3][lr] = av.w;
        Bs[lk + 0][lr] = bv.x; Bs[lk + 1][lr] = bv.y; Bs[lk + 2][lr] = bv.z; Bs[lk + 3][lr] = bv.w;
        __syncthreads();
#pragma unroll
        for (int kk = 0; kk < 8; kk++) {
            float4 a0 = *(const float4*)&As[kk][ty * 4];
            float4 a1 = *(const float4*)&As[kk][64 + ty * 4];
            float4 b0 = *(const float4*)&Bs[kk][tx * 4];
            float4 b1 = *(const float4*)&Bs[kk][64 + tx * 4];
            float ar[8] = {a0.x, a0.y, a0.z, a0.w, a1.x, a1.y, a1.z, a1.w};
            float br[8] = {b0.x, b0.y, b0.z, b0.w, b1.x, b1.y, b1.z, b1.w};
#pragma unroll
            for (int ih = 0; ih < 2; ih++)
#pragma unroll
                for (int i = 0; i < 4; i++)
#pragma unroll
                    for (int jh = 0; jh < 2; jh++)
#pragma unroll
                        for (int j = 0; j < 4; j++)
                            acc[ih][jh][i][j] += ar[ih * 4 + i] * br[jh * 4 + j];
        }
    }
#pragma unroll
    for (int ih = 0; ih < 2; ih++)
#pragma unroll
        for (int i = 0; i < 4; i++) {
            int rm = m0 + ih * 64 + ty * 4 + i;
#pragma unroll
            for (int jh = 0; jh < 2; jh++) {
                int cn = n0 + jh * 64 + tx * 4;
                float4 v = make_float4(acc[ih][jh][i][0], acc[ih][jh][i][1],
                                       acc[ih][jh][i][2], acc[ih][jh][i][3]);
                *(float4*)&g_implicit[(size_t)rm * DD + cn] = v;
            }
        }
}

// ===========================================================================
// Kernel 2: fp32 -> fp16 (screening copy)
// ===========================================================================
__global__ __launch_bounds__(256) void k_tohalf(const float* __restrict__ src,
                                                __half* __restrict__ dst, int n) {
    int i = 4 * (blockIdx.x * 256 + threadIdx.x);
    if (i >= n) return;
    float4 v = *(const float4*)(src + i);
    __half L[4] = {__float2half_rn(v.x), __float2half_rn(v.y),
                   __float2half_rn(v.z), __float2half_rn(v.w)};
    *(uint2*)(dst + i) = *(uint2*)L;
}

// ===========================================================================
// Kernel 3: halfnorm[c] = 0.5 * ||implicit[c]||^2
// ===========================================================================
__global__ __launch_bounds__(256) void k_halfnorm() {
    int warp = threadIdx.x >> 5, lane = threadIdx.x & 31;
    int row = blockIdx.x * 8 + warp;
    const float* p = g_implicit + (size_t)row * DD;
    float s = 0.f;
#pragma unroll
    for (int k = 0; k < DD / 32; k++) {
        float v = p[lane + 32 * k];
        s += v * v;
    }
#pragma unroll
    for (int o = 16; o > 0; o >>= 1) s += __shfl_xor_sync(0xffffffff, s, o);
    if (lane == 0) g_halfnorm[row] = 0.5f * s;
}

// ===========================================================================
// Kernel 4: HMMA screening GEMM + per-row top-4.  512 threads (4x4 warps).
// A tile resident in smem (swizzled); B streamed in k=64 chunks, 4 stages.
// swizzle: phys = row*128 + ((seg ^ (row&7))<<4), seg = 16B column segment.
// ===========================================================================
__device__ __forceinline__ void issue_b(uint32_t st, int ct, int kc, int tid) {
#pragma unroll
    for (int j = 0; j < 2; j++) {
        int idx = j * NTHR + tid;          // 0..1023
        int row = idx >> 3, seg = idx & 7;
        const __half* g = g_ch + (size_t)(ct * Bb_N + row) * DD + kc * Bb_K + seg * 8;
        cp16(st + row * 128 + (((seg ^ (row & 7))) << 4), g);
    }
}

__global__ __launch_bounds__(NTHR, 1) void k_screen_mma() {
    extern __shared__ char dsm[];
    __shared__ float sv[4][128][4];
    __shared__ int   si[4][128][4];

    const uint32_t sa = smem_u32(dsm);            // A resident, 128KB
    const uint32_t sbB = sa + A_BYTES;            // B stages
    const int tid = threadIdx.x;
    const int lane = tid & 31;
    const int wid = tid >> 5;
    const int warp_m = wid >> 2;      // 0..3  (32 rows each)
    const int warp_n = wid & 3;       // 0..3  (32 cols each)
    const int m0 = blockIdx.x * Bb_M;
    const int gID = lane >> 2;        // 0..7
    const int tg  = lane & 3;         // 0..3

    // A-row base (row = warp_m*32 + mt*16 + (lane&15); row&7 == lane&7)
    const uint32_t aRow = (uint32_t)(warp_m * 32 + (lane & 15)) * 128;
    const uint32_t bRow = (uint32_t)(warp_n * 32 + ((lane >> 4) & 1) * 8 + (lane & 7)) * 128;
    const int lxor = lane & 7;

    // running per-row top-4 (owned by tid<128, row = m0+tid)
    float rb0 = 3.4e38f, rb1 = 3.4e38f, rb2 = 3.4e38f, rb3 = 3.4e38f;
    int   ri0 = 0, ri1 = 0, ri2 = 0, ri3 = 0;

    float acc[2][4][4];

    // ---- prologue: resident A (8192 segs) + B stages 0..2 ----
#pragma unroll
    for (int t = 0; t < 16; t++) {
        int idx = t * NTHR + tid;          // 0..8191
        int row = idx >> 6, s = idx & 63;
        int kb = s >> 3, seg = s & 7;
        const __half* g = g_xh + (size_t)(m0 + row) * DD + kb * 64 + seg * 8;
        cp16(sa + kb * KB_BYTES + row * 128 + ((seg ^ (row & 7)) << 4), g);
    }
    issue_b(sbB + 0 * KB_BYTES, 0, 0, tid); CP_COMMIT();
    issue_b(sbB + 1 * KB_BYTES, 0, 1, tid); CP_COMMIT();
    issue_b(sbB + 2 * KB_BYTES, 0, 2, tid); CP_COMMIT();

    for (int q = 0; q < NQ; q++) {
        const int ct = q >> 3;
        const int kc = q & 7;

        CP_WAIT2();          // chunk q (and A, at q=0) resident
        __syncthreads();

        const int qn = q + 3;
        if (qn < NQ)
            issue_b(sbB + (qn & 3) * KB_BYTES, qn >> 3, qn & 7, tid);
        CP_COMMIT();

        if (kc == 0) {
#pragma unroll
            for (int mt = 0; mt < 2; mt++)
#pragma unroll
                for (int nt = 0; nt < 4; nt++)
#pragma unroll
                    for (int e = 0; e < 4; e++) acc[mt][nt][e] = 0.f;
        }

        const uint32_t aBase = sa + kc * KB_BYTES;
        const uint32_t bBase = sbB + (q & 3) * KB_BYTES;
#pragma unroll
        for (int ks = 0; ks < 4; ks++) {
            const uint32_t aSw = (uint32_t)(((ks * 2 + (lane >> 4)) ^ lxor) << 4);
            const uint32_t bSw = (uint32_t)(((ks * 2 + ((lane >> 3) & 1)) ^ lxor) << 4);
            uint32_t aF[2][4], bF[4][2];
#pragma unroll
            for (int mt = 0; mt < 2; mt++)
                LDM4(aF[mt][0], aF[mt][1], aF[mt][2], aF[mt][3],
                     aBase + aRow + mt * (16 * 128) + aSw);
#pragma unroll
            for (int p = 0; p < 2; p++) {
                uint32_t r0, r1, r2, r3;
                LDM4(r0, r1, r2, r3, bBase + bRow + p * (16 * 128) + bSw);
                bF[2 * p][0] = r0; bF[2 * p][1] = r1;
                bF[2 * p + 1][0] = r2; bF[2 * p + 1][1] = r3;
            }
#pragma unroll
            for (int mt = 0; mt < 2; mt++)
#pragma unroll
                for (int nt = 0; nt < 4; nt++) MMA16816(acc[mt][nt], aF[mt], bF[nt]);
        }

        if (kc == 7) {
            // -------- top-4 epilogue for this c-tile --------
#pragma unroll
            for (int mt = 0; mt < 2; mt++) {
#pragma unroll
                for (int half = 0; half < 2; half++) {
                    float b0 = 3.4e38f, b1 = 3.4e38f, b2 = 3.4e38f, b3 = 3.4e38f;
                    int   i0 = 0, i1 = 0, i2 = 0, i3 = 0;
#pragma unroll
                    for (int nt = 0; nt < 4; nt++) {
#pragma unroll
                        for (int j = 0; j < 2; j++) {
                            int c = ct * Bb_N + warp_n * 32 + nt * 8 + tg * 2 + j;
                            float s = __ldg(&g_halfnorm[c]) - acc[mt][nt][2 * half + j];
                            ins4(s, c, b0, b1, b2, b3, i0, i1, i2, i3);
                        }
                    }
#pragma unroll
                    for (int off = 1; off <= 2; off <<= 1) {
                        float ob0 = __shfl_xor_sync(0xffffffff, b0, off);
                        float ob1 = __shfl_xor_sync(0xffffffff, b1, off);
                        float ob2 = __shfl_xor_sync(0xffffffff, b2, off);
                        float ob3 = __shfl_xor_sync(0xffffffff, b3, off);
                        int oi0 = __shfl_xor_sync(0xffffffff, i0, off);
                        int oi1 = __shfl_xor_sync(0xffffffff, i1, off);
                        int oi2 = __shfl_xor_sync(0xffffffff, i2, off);
                        int oi3 = __shfl_xor_sync(0xffffffff, i3, off);
                        ins4(ob0, oi0, b0, b1, b2, b3, i0, i1, i2, i3);
                        ins4(ob1, oi1, b0, b1, b2, b3, i0, i1, i2, i3);
                        ins4(ob2, oi2, b0, b1, b2, b3, i0, i1, i2, i3);
                        ins4(ob3, oi3, b0, b1, b2, b3, i0, i1, i2, i3);
                    }
                    if (tg == 0) {
                        int r = warp_m * 32 + mt * 16 + gID + 8 * half;
                        sv[warp_n][r][0] = b0; sv[warp_n][r][1] = b1;
                        sv[warp_n][r][2] = b2; sv[warp_n][r][3] = b3;
                        si[warp_n][r][0] = i0; si[warp_n][r][1] = i1;
                        si[warp_n][r][2] = i2; si[warp_n][r][3] = i3;
                    }
                }
            }
            __syncthreads();
            if (tid < 128) {
#pragma unroll
                for (int wn = 0; wn < 4; wn++)
#pragma unroll
                    for (int s = 0; s < 4; s++)
                        ins4(sv[wn][tid][s], si[wn][tid][s],
                             rb0, rb1, rb2, rb3, ri0, ri1, ri2, ri3);
            }
            __syncthreads();
        }
    }

    if (tid < 128) {
        int gm = m0 + tid;
        g_cand[gm * 4 + 0] = ri0;
        g_cand[gm * 4 + 1] = ri1;
        g_cand[gm * 4 + 2] = ri2;
        g_cand[gm * 4 + 3] = ri3;
    }
}

// ===========================================================================
// Kernel 5: exact fp32 rescore of the 4 candidates. One warp per row.
// ===========================================================================
__global__ __launch_bounds__(256) void k_rescore(const float* __restrict__ X,
                                                 float* __restrict__ out_idx_f) {
    const int warp = threadIdx.x >> 5, lane = threadIdx.x & 31;
    const int m = blockIdx.x * 8 + warp;
    const float* xr = X + (size_t)m * DD;

    float4 xv[4];
#pragma unroll
    for (int t = 0; t < 4; t++) xv[t] = ((const float4*)xr)[lane + 32 * t];

    float bestv = 3.4e38f;
    int   besti = 0x7fffffff;
#pragma unroll
    for (int k = 0; k < 4; k++) {
        int ci = g_cand[m * 4 + k];
        const float4* cr = (const float4*)(g_implicit + (size_t)ci * DD);
        float dot = 0.f;
#pragma unroll
        for (int t = 0; t < 4; t++) {
            float4 cv = cr[lane + 32 * t];
            dot += xv[t].x * cv.x + xv[t].y * cv.y + xv[t].z * cv.z + xv[t].w * cv.w;
        }
#pragma unroll
        for (int o = 16; o > 0; o >>= 1) dot += __shfl_xor_sync(0xffffffff, dot, o);
        float s = g_halfnorm[ci] - dot;
        if (s < bestv || (s == bestv && ci < besti)) { bestv = s; besti = ci; }
    }
    if (lane == 0) {
        g_idx[m] = besti;
        out_idx_f[m] = (float)besti;
    }
}

// ===========================================================================
// Kernel 6: rotation trick + per-row commit sum. One block per x-row.
// ===========================================================================
__global__ __launch_bounds__(128) void k_rot(const float* __restrict__ X,
                                             float* __restrict__ outq) {
    __shared__ float red[4][4];
    const int m = blockIdx.x;
    const int t = threadIdx.x;
    const float* xr = X + (size_t)m * DD;
    const float* qr = g_implicit + (size_t)g_idx[m] * DD;

    float4 xv = ((const float4*)xr)[t];
    float4 qv = ((const float4*)qr)[t];

    float sx  = xv.x * xv.x + xv.y * xv.y + xv.z * xv.z + xv.w * xv.w;
    float sq  = qv.x * qv.x + qv.y * qv.y + qv.z * qv.z + qv.w * qv.w;
    float sxq = xv.x * qv.x + xv.y * qv.y + xv.z * qv.z + xv.w * qv.w;
    float d0 = xv.x - qv.x + 1e-6f, d1 = xv.y - qv.y + 1e-6f;
    float d2 = xv.z - qv.z + 1e-6f, d3 = xv.w - qv.w + 1e-6f;
    float sc = d0 * d0 + d1 * d1 + d2 * d2 + d3 * d3;

#pragma unroll
    for (int o = 16; o > 0; o >>= 1) {
        sx  += __shfl_xor_sync(0xffffffff, sx, o);
        sq  += __shfl_xor_sync(0xffffffff, sq, o);
        sxq += __shfl_xor_sync(0xffffffff, sxq, o);
        sc  += __shfl_xor_sync(0xffffffff, sc, o);
    }
    int warp = t >> 5, lane = t & 31;
    if (lane == 0) { red[warp][0] = sx; red[warp][1] = sq; red[warp][2] = sxq; red[warp][3] = sc; }
    __syncthreads();
    sx  = red[0][0] + red[1][0] + red[2][0] + red[3][0];
    sq  = red[0][1] + red[1][1] + red[2][1] + red[3][1];
    sxq = red[0][2] + red[1][2] + red[2][2] + red[3][2];
    sc  = red[0][3] + red[1][3] + red[2][3] + red[3][3];

    if (t == 0) g_commit[m] = sc;

    float norm_x = sqrtf(sx), norm_q = sqrtf(sq);
    float nx = fmaxf(norm_x, 1e-6f);
    float nq = fmaxf(norm_q, 1e-6f);
    float uq2 = sx / (nx * nx) + sq / (nq * nq) + 2.f * sxq / (nx * nq);
    float nuq = sqrtf(fmaxf(uq2, 0.f));
    float wden = fmaxf(nuq, 1e-12f);
    float e_w = (sx / nx + sxq / nq) / wden;
    float e_u = sx / nx;
    float c1 = 2.f * e_w / wden;
    float c2 = 2.f * e_u;
    float scale = norm_q / nx;
    float coef_x = (1.f - c1 / nx) * scale;
    float coef_q = ((c2 - c1) / nq) * scale;

    float4 ov;
    ov.x = coef_x * xv.x + coef_q * qv.x;
    ov.y = coef_x * xv.y + coef_q * qv.y;
    ov.z = coef_x * xv.z + coef_q * qv.z;
    ov.w = coef_x * xv.w + coef_q * qv.w;
    ((float4*)(outq + (size_t)m * DD))[t] = ov;
}

// ===========================================================================
// Kernel 7: deterministic loss reduction
// ===========================================================================
__global__ __launch_bounds__(256) void k_loss(float* __restrict__ out_loss) {
    __shared__ float s[256];
    float v = 0.f;
    for (int i = threadIdx.x; i < MM; i += 256) v += g_commit[i];
    s[threadIdx.x] = v;
    __syncthreads();
    for (int o = 128; o > 0; o >>= 1) {
        if (threadIdx.x < o) s[threadIdx.x] += s[threadIdx.x + o];
        __syncthreads();
    }
    if (threadIdx.x == 0) out_loss[0] = s[0] / (float)MM;
}

// ===========================================================================
extern "C" void kernel_launch(void* const* d_in, const int* in_sizes, int n_in,
                              void* d_out, int out_size) {
    const float* x  = (const float*)d_in[0];
    const float* cb = (const float*)d_in[1];
    const float* Wm = (const float*)d_in[2];
    float* out = (float*)d_out;

    int idx_off  = out_size - MM - 1;
    int loss_off = out_size - 1;

    static bool attr_done = false;
    if (!attr_done) {
        cudaFuncSetAttribute(k_screen_mma, cudaFuncAttributeMaxDynamicSharedMemorySize, SMEM_DYN);
        attr_done = true;
    }

    __half *xh, *ch; float* imp;
    cudaGetSymbolAddress((void**)&xh, g_xh);
    cudaGetSymbolAddress((void**)&ch, g_ch);
    cudaGetSymbolAddress((void**)&imp, g_implicit);

    k_implicit<<<dim3(CC / 128, DD / 128), 256>>>(cb, Wm);
    k_tohalf<<<(MM * DD / 4 + 255) / 256, 256>>>(x, xh, MM * DD);
    k_tohalf<<<(CC * DD / 4 + 255) / 256, 256>>>(imp, ch, CC * DD);
    k_halfnorm<<<CC / 8, 256>>>();
    k_screen_mma<<<MM / Bb_M, NTHR, SMEM_DYN>>>();
    k_rescore<<<MM / 8, 256>>>(x, out + idx_off);
    k_rot<<<MM, 128>>>(x, out);
    k_loss<<<1, 256>>>(out + loss_off);
}